// round 5
// baseline (speedup 1.0000x reference)
#include <cuda_runtime.h>
#include <math_constants.h>

#define SEQ 2048
#define DM  512
#define NB  2
#define NH  8
#define DH  64

__device__ __align__(16) float g_Q[NB*NH*SEQ*DH];
__device__ __align__(16) float g_K[NB*NH*SEQ*DH];
__device__ __align__(16) float g_V[NB*NH*SEQ*DH];
__device__ __align__(16) float g_O[NB*SEQ*DM];

// C[m][j] = sum_k A[m][k] * W[j][k]   (A: [4096,512] row-major, W: [512,512] row-major)
// MODE 0/1/2: A = x param, write g_Q/g_K/g_V in head-split layout [b][h][n][dh]
// MODE 3:     A = g_O, write outParam plain [m][j]
template<int MODE>
__global__ void __launch_bounds__(256) gemm_nt_kernel(const float* __restrict__ A,
                                                      const float* __restrict__ W,
                                                      float* __restrict__ outParam) {
    __shared__ __align__(16) float As[32][68];   // k-major: As[k][m]
    __shared__ __align__(16) float Ws[32][68];   // Ws[k][j]
    const int t  = threadIdx.x;
    const int tx = t & 15, ty = t >> 4;
    const int m0 = blockIdx.y * 64;
    const int j0 = blockIdx.x * 64;

    const float* Ap = (MODE == 3) ? (const float*)g_O : A;

    float acc[4][4];
#pragma unroll
    for (int i = 0; i < 4; i++)
#pragma unroll
        for (int j = 0; j < 4; j++) acc[i][j] = 0.f;

    const int r   = t & 63;      // row within tile
    const int c4b = t >> 6;      // float4 column base
    const float* Arow = Ap + (size_t)(m0 + r) * DM;
    const float* Wrow = W  + (size_t)(j0 + r) * DM;

    for (int k0 = 0; k0 < DM; k0 += 32) {
        __syncthreads();
#pragma unroll
        for (int p = 0; p < 2; p++) {
            int c4 = c4b + 4 * p;
            float4 av = *(const float4*)(Arow + k0 + c4 * 4);
            float4 wv = *(const float4*)(Wrow + k0 + c4 * 4);
            As[c4*4+0][r] = av.x; As[c4*4+1][r] = av.y;
            As[c4*4+2][r] = av.z; As[c4*4+3][r] = av.w;
            Ws[c4*4+0][r] = wv.x; Ws[c4*4+1][r] = wv.y;
            Ws[c4*4+2][r] = wv.z; Ws[c4*4+3][r] = wv.w;
        }
        __syncthreads();
#pragma unroll
        for (int k = 0; k < 32; k++) {
            float4 a4 = *(const float4*)&As[k][ty*4];
            float4 w4 = *(const float4*)&Ws[k][tx*4];
            float a[4] = {a4.x, a4.y, a4.z, a4.w};
            float w[4] = {w4.x, w4.y, w4.z, w4.w};
#pragma unroll
            for (int i = 0; i < 4; i++)
#pragma unroll
                for (int j = 0; j < 4; j++)
                    acc[i][j] = fmaf(a[i], w[j], acc[i][j]);
        }
    }

#pragma unroll
    for (int i = 0; i < 4; i++) {
        int m = m0 + ty*4 + i;
        float4 o = make_float4(acc[i][0], acc[i][1], acc[i][2], acc[i][3]);
        if (MODE == 3) {
            *(float4*)(outParam + (size_t)m * DM + j0 + tx*4) = o;
        } else {
            float* dst = (MODE == 0) ? g_Q : (MODE == 1) ? g_K : g_V;
            int b = m >> 11, n = m & (SEQ - 1);
            int h = j0 >> 6;               // block spans exactly one head
            *(float4*)(dst + ((size_t)(b*NH + h)*SEQ + n) * DH + tx*4) = o;
        }
    }
}

// Tiled hyperbolic attention with ONLINE MAX softmax (flash-style).
// Scores can be ~ -130 => exp underflows without max subtraction (the round 1-4 bug).
__global__ void __launch_bounds__(256) attn_kernel(const float* __restrict__ p_logc,
                                                   const float* __restrict__ p_logb) {
    extern __shared__ float sm[];
    float* Qs = sm;              // [64][68] d-major: Qs[d][i]
    float* Ks = sm + 64*68;      // [64][68] d-major: Ks[d][j]
    float* Vs = sm + 2*64*68;    // [64][68] j-major: Vs[j][d]
    float* Ps = sm + 3*64*68;    // [64][68] row-major: Ps[i][j]
    float* qn = sm + 4*64*68;    // [64]
    float* kn = qn + 64;         // [64]

    const int t  = threadIdx.x;
    const int tx = t & 15, ty = t >> 4;
    const int qt = (int)(gridDim.x - 1 - blockIdx.x);   // heavy blocks first
    const int h  = blockIdx.y, b = blockIdx.z;
    const int bh = b * NH + h;

    const float c    = log1pf(__expf(*p_logc));
    const float beta = log1pf(__expf(*p_logb)) + 0.5f;

    // ---- load Q tile transposed ----
    {
        const int i   = t & 63;
        const int c4b = t >> 6;
        const float* row = g_Q + ((size_t)bh * SEQ + qt * 64 + i) * DH;
#pragma unroll
        for (int p = 0; p < 4; p++) {
            int c4 = c4b + 4 * p;
            float4 v = *(const float4*)(row + c4 * 4);
            Qs[(c4*4+0)*68 + i] = v.x;
            Qs[(c4*4+1)*68 + i] = v.y;
            Qs[(c4*4+2)*68 + i] = v.z;
            Qs[(c4*4+3)*68 + i] = v.w;
        }
    }
    __syncthreads();
    if (t < 64) {
        float s = 0.f;
#pragma unroll 8
        for (int d = 0; d < 64; d++) { float q = Qs[d*68 + t]; s = fmaf(q, q, s); }
        qn[t] = s;
    }

    float acc[4][4];
    float mrow[4], lpart[4];
#pragma unroll
    for (int i = 0; i < 4; i++) {
        mrow[i] = -CUDART_INF_F;
        lpart[i] = 0.f;
#pragma unroll
        for (int j = 0; j < 4; j++) acc[i][j] = 0.f;
    }

    for (int kt = 0; kt <= qt; kt++) {
        __syncthreads();   // prior PV reads (and qn init) done before overwrite
        const float* Kg = g_K + ((size_t)bh * SEQ + kt * 64) * DH;
        const float* Vg = g_V + ((size_t)bh * SEQ + kt * 64) * DH;
        {   // K transposed
            const int j   = t & 63;
            const int c4b = t >> 6;
            const float* row = Kg + j * DH;
#pragma unroll
            for (int p = 0; p < 4; p++) {
                int c4 = c4b + 4 * p;
                float4 v = *(const float4*)(row + c4 * 4);
                Ks[(c4*4+0)*68 + j] = v.x;
                Ks[(c4*4+1)*68 + j] = v.y;
                Ks[(c4*4+2)*68 + j] = v.z;
                Ks[(c4*4+3)*68 + j] = v.w;
            }
        }
        {   // V row-major
#pragma unroll
            for (int p = 0; p < 4; p++) {
                int f = t + 256 * p;
                int j = f >> 4, c4 = f & 15;
                *(float4*)&Vs[j*68 + c4*4] = *(const float4*)(Vg + j * DH + c4 * 4);
            }
        }
        __syncthreads();
        if (t < 64) {
            float s = 0.f;
#pragma unroll 8
            for (int d = 0; d < 64; d++) { float k = Ks[d*68 + t]; s = fmaf(k, k, s); }
            kn[t] = s;
        }
        __syncthreads();

        // ---- S = Q K^T ----
        float sv[4][4];
#pragma unroll
        for (int i = 0; i < 4; i++)
#pragma unroll
            for (int j = 0; j < 4; j++) sv[i][j] = 0.f;
#pragma unroll 8
        for (int d = 0; d < 64; d++) {
            float4 q4 = *(const float4*)&Qs[d*68 + ty*4];
            float4 k4 = *(const float4*)&Ks[d*68 + tx*4];
            float q[4]  = {q4.x, q4.y, q4.z, q4.w};
            float kk[4] = {k4.x, k4.y, k4.z, k4.w};
#pragma unroll
            for (int i = 0; i < 4; i++)
#pragma unroll
                for (int j = 0; j < 4; j++)
                    sv[i][j] = fmaf(q[i], kk[j], sv[i][j]);
        }

        // ---- scores s = -beta * sqrt((max(qn-2qk+kn,0)+1e-8) * (1+c*(qn+kn))), causal mask ----
        float s[4][4];
        const int gi0 = qt*64 + ty*4, gj0 = kt*64 + tx*4;
#pragma unroll
        for (int i = 0; i < 4; i++) {
            float qni = qn[ty*4 + i];
#pragma unroll
            for (int j = 0; j < 4; j++) {
                float a    = qni + kn[tx*4 + j];
                float diff = fmaxf(fmaf(-2.f, sv[i][j], a), 0.f) + 1e-8f;
                float prod = diff * fmaf(c, a, 1.f);
                float dist = prod * rsqrtf(prod);                 // sqrt(prod)
                s[i][j] = (gj0 + j <= gi0 + i) ? (-beta * dist) : -CUDART_INF_F;
            }
        }

        // ---- online max across the 16-lane tx-group ----
        float mt[4];
#pragma unroll
        for (int i = 0; i < 4; i++)
            mt[i] = fmaxf(fmaxf(s[i][0], s[i][1]), fmaxf(s[i][2], s[i][3]));
#pragma unroll
        for (int off = 8; off > 0; off >>= 1)
#pragma unroll
            for (int i = 0; i < 4; i++)
                mt[i] = fmaxf(mt[i], __shfl_xor_sync(0xffffffffu, mt[i], off));

        float w[4][4];
#pragma unroll
        for (int i = 0; i < 4; i++) {
            float mnew  = fmaxf(mrow[i], mt[i]);           // finite: col 0 of kt=0 unmasked
            float scale = __expf(mrow[i] - mnew);          // first tile: exp(-inf)=0
            mrow[i] = mnew;
            float rs = 0.f;
#pragma unroll
            for (int j = 0; j < 4; j++) {
                float wv = __expf(s[i][j] - mnew);         // masked: exp(-inf)=0
                w[i][j] = wv;
                rs += wv;
            }
            lpart[i] = lpart[i] * scale + rs;
#pragma unroll
            for (int d = 0; d < 4; d++) acc[i][d] *= scale;
        }

        // ---- P tile to smem, then O += P V ----
#pragma unroll
        for (int i = 0; i < 4; i++)
            *(float4*)&Ps[(ty*4 + i)*68 + tx*4] = make_float4(w[i][0], w[i][1], w[i][2], w[i][3]);
        __syncthreads();

#pragma unroll
        for (int jj0 = 0; jj0 < 64; jj0 += 4) {
            float p[4][4];
#pragma unroll
            for (int i = 0; i < 4; i++) {
                float4 p4 = *(const float4*)&Ps[(ty*4 + i)*68 + jj0];
                p[i][0] = p4.x; p[i][1] = p4.y; p[i][2] = p4.z; p[i][3] = p4.w;
            }
#pragma unroll
            for (int q = 0; q < 4; q++) {
                float4 v4 = *(const float4*)&Vs[(jj0 + q)*68 + tx*4];
                float v[4] = {v4.x, v4.y, v4.z, v4.w};
#pragma unroll
                for (int i = 0; i < 4; i++)
#pragma unroll
                    for (int d = 0; d < 4; d++)
                        acc[i][d] = fmaf(p[i][q], v[d], acc[i][d]);
            }
        }
    }

    // ---- reduce row sums across tx-group, normalize, write O [b][n][h*64+d] ----
#pragma unroll
    for (int off = 8; off > 0; off >>= 1)
#pragma unroll
        for (int i = 0; i < 4; i++)
            lpart[i] += __shfl_xor_sync(0xffffffffu, lpart[i], off);

    float* Og = g_O + ((size_t)b * SEQ + qt * 64) * DM + h * DH;
#pragma unroll
    for (int i = 0; i < 4; i++) {
        float inv = 1.f / lpart[i];
        float4 o = make_float4(acc[i][0]*inv, acc[i][1]*inv, acc[i][2]*inv, acc[i][3]*inv);
        *(float4*)(Og + (size_t)(ty*4 + i) * DM + tx*4) = o;
    }
}

extern "C" void kernel_launch(void* const* d_in, const int* in_sizes, int n_in,
                              void* d_out, int out_size) {
    // metadata order: x, Wq, Wk, Wv, Wo, log_c, log_beta (size-checked fallback)
    const float* x    = (const float*)d_in[0];
    const float* Wq   = (const float*)d_in[1];
    const float* Wk   = (const float*)d_in[2];
    const float* Wv   = (const float*)d_in[3];
    const float* Wo   = (const float*)d_in[4];
    const float* logc = (const float*)d_in[5];
    const float* logb = (const float*)d_in[6];
    if (in_sizes[0] != NB * SEQ * DM) {
        const float* xf = nullptr; const float* ws[4] = {}; const float* sc[2] = {};
        int nw = 0, ns = 0;
        for (int i = 0; i < n_in; i++) {
            if (in_sizes[i] == NB * SEQ * DM)          xf = (const float*)d_in[i];
            else if (in_sizes[i] == DM * DM && nw < 4) ws[nw++] = (const float*)d_in[i];
            else if (in_sizes[i] == 1 && ns < 2)       sc[ns++] = (const float*)d_in[i];
        }
        if (xf && nw == 4 && ns == 2) {
            x = xf; Wq = ws[0]; Wk = ws[1]; Wv = ws[2]; Wo = ws[3];
            logc = sc[0]; logb = sc[1];
        }
    }
    float* out = (float*)d_out;

    size_t smem = (size_t)(4*64*68 + 2*64) * sizeof(float);   // 70144 B
    cudaFuncSetAttribute(attn_kernel, cudaFuncAttributeMaxDynamicSharedMemorySize, (int)smem);

    dim3 ggrid(DM / 64, (NB * SEQ) / 64);
    gemm_nt_kernel<0><<<ggrid, 256>>>(x, Wq, nullptr);
    gemm_nt_kernel<1><<<ggrid, 256>>>(x, Wk, nullptr);
    gemm_nt_kernel<2><<<ggrid, 256>>>(x, Wv, nullptr);

    dim3 agrid(SEQ / 64, NH, NB);
    attn_kernel<<<agrid, 256, smem>>>(logc, logb);

    gemm_nt_kernel<3><<<ggrid, 256>>>(nullptr, Wo, out);
}

// round 7
// speedup vs baseline: 1.4469x; 1.4469x over previous
#include <cuda_runtime.h>
#include <cuda_bf16.h>
#include <math_constants.h>
#include <cstdint>

#define SEQ 2048
#define DM  512
#define NB  2
#define NH  8
#define DH  64
#define MROWS (NB*SEQ)   // 4096

__device__ __align__(16) float g_Q[NB*NH*SEQ*DH];
__device__ __align__(16) float g_K[NB*NH*SEQ*DH];
__device__ __align__(16) float g_V[NB*NH*SEQ*DH];
__device__ __align__(16) float g_O[NB*SEQ*DM];

__device__ __align__(16) __nv_bfloat16 g_xh[MROWS*DM];
__device__ __align__(16) __nv_bfloat16 g_xl[MROWS*DM];
__device__ __align__(16) __nv_bfloat16 g_Wh[4*DM*DM];
__device__ __align__(16) __nv_bfloat16 g_Wl[4*DM*DM];
__device__ __align__(16) __nv_bfloat16 g_Oh[MROWS*DM];
__device__ __align__(16) __nv_bfloat16 g_Ol[MROWS*DM];

// ---------------- warp-MMA helpers (sm_80+ ISA, safe on plain sm_103) ----------------
__device__ __forceinline__ uint32_t smem_u32(const void* p) {
    uint32_t a;
    asm("{ .reg .u64 t; cvta.to.shared.u64 t, %1; cvt.u32.u64 %0, t; }" : "=r"(a) : "l"(p));
    return a;
}
__device__ __forceinline__ void ldm_x4(uint32_t* r, uint32_t addr) {
    asm volatile("ldmatrix.sync.aligned.m8n8.x4.shared.b16 {%0,%1,%2,%3}, [%4];"
                 : "=r"(r[0]), "=r"(r[1]), "=r"(r[2]), "=r"(r[3]) : "r"(addr));
}
__device__ __forceinline__ void mma_bf16(float* d, const uint32_t* a, const uint32_t* b) {
    asm volatile("mma.sync.aligned.m16n8k16.row.col.f32.bf16.bf16.f32 "
                 "{%0,%1,%2,%3}, {%4,%5,%6,%7}, {%8,%9}, {%0,%1,%2,%3};"
                 : "+f"(d[0]), "+f"(d[1]), "+f"(d[2]), "+f"(d[3])
                 : "r"(a[0]), "r"(a[1]), "r"(a[2]), "r"(a[3]), "r"(b[0]), "r"(b[1]));
}

// ---------------- fp32 -> bf16 (hi, lo) split conversion ----------------
__global__ void __launch_bounds__(256) cvt_kernel(const float* __restrict__ src,
                                                  int dst_sel, int n) {
    int i = (blockIdx.x * 256 + threadIdx.x) * 4;
    if (i >= n) return;
    const float* s = (dst_sel == 5) ? (const float*)g_O : src;
    __nv_bfloat16 *dh, *dl;
    if (dst_sel == 0)      { dh = g_xh; dl = g_xl; }
    else if (dst_sel == 5) { dh = g_Oh; dl = g_Ol; }
    else { dh = g_Wh + (size_t)(dst_sel-1)*DM*DM; dl = g_Wl + (size_t)(dst_sel-1)*DM*DM; }
    float4 v = *(const float4*)(s + i);
    float vv[4] = {v.x, v.y, v.z, v.w};
#pragma unroll
    for (int k = 0; k < 4; k++) {
        __nv_bfloat16 h = __float2bfloat16(vv[k]);
        dh[i + k] = h;
        dl[i + k] = __float2bfloat16(vv[k] - __bfloat162float(h));
    }
}

// ---------------- split-bf16 GEMM via mma.sync: C[m][j] = sum_k A[m][k] * W[j][k] ----------------
// CTA: 128x128 tile, 8 warps, each warp 32x64 (2 m16-tiles x 8 n8-tiles), K slab = 32.
// MODE 0: A = g_xh/l, W = g_Wh/l + z*DM*DM (z=blockIdx.z selects Q/K/V), head-split output
// MODE 1: A = g_Oh/l, W index 3 (Wo), plain [m][j] output
#define ASTR 40   // bf16 elems per smem row (80 B) -> conflict-free ldmatrix

template<int MODE>
__global__ void __launch_bounds__(256) mma_gemm_kernel(float* __restrict__ outp) {
    __shared__ __align__(16) __nv_bfloat16 sAh[128*ASTR], sAl[128*ASTR];
    __shared__ __align__(16) __nv_bfloat16 sBh[128*ASTR], sBl[128*ASTR];

    const int t = threadIdx.x, lane = t & 31, w = t >> 5;
    const int wm = w & 3, wn = w >> 2;            // warp rows wm*32, cols wn*64
    const int m0 = blockIdx.y * 128, j0 = blockIdx.x * 128;
    const int wsel = (MODE == 0) ? (int)blockIdx.z : 3;

    const __nv_bfloat16* Ahp = (MODE == 0) ? g_xh : g_Oh;
    const __nv_bfloat16* Alp = (MODE == 0) ? g_xl : g_Ol;
    const __nv_bfloat16* Whp = g_Wh + (size_t)wsel * DM * DM;
    const __nv_bfloat16* Wlp = g_Wl + (size_t)wsel * DM * DM;

    float acc[2][8][4];
#pragma unroll
    for (int mt = 0; mt < 2; mt++)
#pragma unroll
        for (int nt = 0; nt < 8; nt++)
#pragma unroll
            for (int e = 0; e < 4; e++) acc[mt][nt][e] = 0.f;

    // ldmatrix smem addresses (byte offsets within padded tiles)
    const int arow = wm*32 + (lane & 15);
    const int boff = ((lane >> 4) & 1) * 8;               // +8 elems for k-half
    const int brow = wn*64 + (lane & 7) + ((lane >> 4) & 1) * 8;
    const int bcol = ((lane >> 3) & 1) * 8;

    for (int s = 0; s < DM/32; s++) {
        __syncthreads();
        // load 32-wide K slab: 4 x 16B chunks per row per buffer
#pragma unroll
        for (int p = 0; p < 2; p++) {
            int id = t + 256 * p;                 // 0..511
            int r = id >> 2, cc = id & 3;
            const size_t ga = (size_t)(m0 + r) * DM + s*32 + cc*8;
            const size_t gb = (size_t)(j0 + r) * DM + s*32 + cc*8;
            *(uint4*)(sAh + r*ASTR + cc*8) = *(const uint4*)(Ahp + ga);
            *(uint4*)(sAl + r*ASTR + cc*8) = *(const uint4*)(Alp + ga);
            *(uint4*)(sBh + r*ASTR + cc*8) = *(const uint4*)(Whp + gb);
            *(uint4*)(sBl + r*ASTR + cc*8) = *(const uint4*)(Wlp + gb);
        }
        __syncthreads();

#pragma unroll
        for (int ks = 0; ks < 2; ks++) {
            uint32_t ah[2][4], al[2][4];
#pragma unroll
            for (int mt = 0; mt < 2; mt++) {
                ldm_x4(ah[mt], smem_u32(&sAh[(arow + mt*16)*ASTR + ks*16 + boff]));
                ldm_x4(al[mt], smem_u32(&sAl[(arow + mt*16)*ASTR + ks*16 + boff]));
            }
            uint32_t bh[8][2], bl[8][2];
#pragma unroll
            for (int pr = 0; pr < 4; pr++) {
                uint32_t r4[4];
                ldm_x4(r4, smem_u32(&sBh[(brow + pr*16)*ASTR + ks*16 + bcol]));
                bh[2*pr][0] = r4[0]; bh[2*pr][1] = r4[1];
                bh[2*pr+1][0] = r4[2]; bh[2*pr+1][1] = r4[3];
                ldm_x4(r4, smem_u32(&sBl[(brow + pr*16)*ASTR + ks*16 + bcol]));
                bl[2*pr][0] = r4[0]; bl[2*pr][1] = r4[1];
                bl[2*pr+1][0] = r4[2]; bl[2*pr+1][1] = r4[3];
            }
#pragma unroll
            for (int mt = 0; mt < 2; mt++)
#pragma unroll
                for (int nt = 0; nt < 8; nt++) {
                    mma_bf16(acc[mt][nt], ah[mt], bh[nt]);   // hi*hi
                    mma_bf16(acc[mt][nt], ah[mt], bl[nt]);   // hi*lo
                    mma_bf16(acc[mt][nt], al[mt], bh[nt]);   // lo*hi
                }
        }
    }

    // ---- epilogue ----
    const int gid = lane >> 2, tig = lane & 3;
#pragma unroll
    for (int mt = 0; mt < 2; mt++) {
#pragma unroll
        for (int nt = 0; nt < 8; nt++) {
            const int mrow = m0 + wm*32 + mt*16 + gid;
            const int jcol = j0 + wn*64 + nt*8 + tig*2;
            float2 lo = make_float2(acc[mt][nt][0], acc[mt][nt][1]);
            float2 hi = make_float2(acc[mt][nt][2], acc[mt][nt][3]);
            if (MODE == 1) {
                *(float2*)(outp + (size_t)mrow * DM + jcol)     = lo;
                *(float2*)(outp + (size_t)(mrow+8) * DM + jcol) = hi;
            } else {
                float* dstb = (blockIdx.z == 0) ? g_Q : (blockIdx.z == 1) ? g_K : g_V;
                const int h = jcol >> 6, d = jcol & (DH-1);
                const int b0r = mrow >> 11, n0r = mrow & (SEQ-1);
                float* base = dstb + ((size_t)(b0r*NH + h) * SEQ) * DH + d;
                *(float2*)(base + (size_t)n0r * DH)       = lo;
                *(float2*)(base + (size_t)(n0r + 8) * DH) = hi;
            }
        }
    }
}

// ---------------- Tiled hyperbolic attention, online-max softmax (round-5 passing version) ----------------
__global__ void __launch_bounds__(256) attn_kernel(const float* __restrict__ p_logc,
                                                   const float* __restrict__ p_logb) {
    extern __shared__ float sm[];
    float* Qs = sm;
    float* Ks = sm + 64*68;
    float* Vs = sm + 2*64*68;
    float* Ps = sm + 3*64*68;
    float* qn = sm + 4*64*68;
    float* kn = qn + 64;

    const int t  = threadIdx.x;
    const int tx = t & 15, ty = t >> 4;
    const int qt = (int)(gridDim.x - 1 - blockIdx.x);
    const int h  = blockIdx.y, b = blockIdx.z;
    const int bh = b * NH + h;

    const float c    = log1pf(__expf(*p_logc));
    const float beta = log1pf(__expf(*p_logb)) + 0.5f;

    {
        const int i   = t & 63;
        const int c4b = t >> 6;
        const float* row = g_Q + ((size_t)bh * SEQ + qt * 64 + i) * DH;
#pragma unroll
        for (int p = 0; p < 4; p++) {
            int c4 = c4b + 4 * p;
            float4 v = *(const float4*)(row + c4 * 4);
            Qs[(c4*4+0)*68 + i] = v.x;
            Qs[(c4*4+1)*68 + i] = v.y;
            Qs[(c4*4+2)*68 + i] = v.z;
            Qs[(c4*4+3)*68 + i] = v.w;
        }
    }
    __syncthreads();
    if (t < 64) {
        float s = 0.f;
#pragma unroll 8
        for (int d = 0; d < 64; d++) { float q = Qs[d*68 + t]; s = fmaf(q, q, s); }
        qn[t] = s;
    }

    float acc[4][4];
    float mrow[4], lpart[4];
#pragma unroll
    for (int i = 0; i < 4; i++) {
        mrow[i] = -CUDART_INF_F;
        lpart[i] = 0.f;
#pragma unroll
        for (int j = 0; j < 4; j++) acc[i][j] = 0.f;
    }

    for (int kt = 0; kt <= qt; kt++) {
        __syncthreads();
        const float* Kg = g_K + ((size_t)bh * SEQ + kt * 64) * DH;
        const float* Vg = g_V + ((size_t)bh * SEQ + kt * 64) * DH;
        {
            const int j   = t & 63;
            const int c4b = t >> 6;
            const float* row = Kg + j * DH;
#pragma unroll
            for (int p = 0; p < 4; p++) {
                int c4 = c4b + 4 * p;
                float4 v = *(const float4*)(row + c4 * 4);
                Ks[(c4*4+0)*68 + j] = v.x;
                Ks[(c4*4+1)*68 + j] = v.y;
                Ks[(c4*4+2)*68 + j] = v.z;
                Ks[(c4*4+3)*68 + j] = v.w;
            }
        }
        {
#pragma unroll
            for (int p = 0; p < 4; p++) {
                int f = t + 256 * p;
                int j = f >> 4, c4 = f & 15;
                *(float4*)&Vs[j*68 + c4*4] = *(const float4*)(Vg + j * DH + c4 * 4);
            }
        }
        __syncthreads();
        if (t < 64) {
            float s = 0.f;
#pragma unroll 8
            for (int d = 0; d < 64; d++) { float k = Ks[d*68 + t]; s = fmaf(k, k, s); }
            kn[t] = s;
        }
        __syncthreads();

        float sv[4][4];
#pragma unroll
        for (int i = 0; i < 4; i++)
#pragma unroll
            for (int j = 0; j < 4; j++) sv[i][j] = 0.f;
#pragma unroll 8
        for (int d = 0; d < 64; d++) {
            float4 q4 = *(const float4*)&Qs[d*68 + ty*4];
            float4 k4 = *(const float4*)&Ks[d*68 + tx*4];
            float q[4]  = {q4.x, q4.y, q4.z, q4.w};
            float kk[4] = {k4.x, k4.y, k4.z, k4.w};
#pragma unroll
            for (int i = 0; i < 4; i++)
#pragma unroll
                for (int j = 0; j < 4; j++)
                    sv[i][j] = fmaf(q[i], kk[j], sv[i][j]);
        }

        float s[4][4];
        const int gi0 = qt*64 + ty*4, gj0 = kt*64 + tx*4;
#pragma unroll
        for (int i = 0; i < 4; i++) {
            float qni = qn[ty*4 + i];
#pragma unroll
            for (int j = 0; j < 4; j++) {
                float a    = qni + kn[tx*4 + j];
                float diff = fmaxf(fmaf(-2.f, sv[i][j], a), 0.f) + 1e-8f;
                float prod = diff * fmaf(c, a, 1.f);
                float dist = prod * rsqrtf(prod);
                s[i][j] = (gj0 + j <= gi0 + i) ? (-beta * dist) : -CUDART_INF_F;
            }
        }

        float mt[4];
#pragma unroll
        for (int i = 0; i < 4; i++)
            mt[i] = fmaxf(fmaxf(s[i][0], s[i][1]), fmaxf(s[i][2], s[i][3]));
#pragma unroll
        for (int off = 8; off > 0; off >>= 1)
#pragma unroll
            for (int i = 0; i < 4; i++)
                mt[i] = fmaxf(mt[i], __shfl_xor_sync(0xffffffffu, mt[i], off));

        float w[4][4];
#pragma unroll
        for (int i = 0; i < 4; i++) {
            float mnew  = fmaxf(mrow[i], mt[i]);
            float scale = __expf(mrow[i] - mnew);
            mrow[i] = mnew;
            float rs = 0.f;
#pragma unroll
            for (int j = 0; j < 4; j++) {
                float wv = __expf(s[i][j] - mnew);
                w[i][j] = wv;
                rs += wv;
            }
            lpart[i] = lpart[i] * scale + rs;
#pragma unroll
            for (int d = 0; d < 4; d++) acc[i][d] *= scale;
        }

#pragma unroll
        for (int i = 0; i < 4; i++)
            *(float4*)&Ps[(ty*4 + i)*68 + tx*4] = make_float4(w[i][0], w[i][1], w[i][2], w[i][3]);
        __syncthreads();

#pragma unroll
        for (int jj0 = 0; jj0 < 64; jj0 += 4) {
            float p[4][4];
#pragma unroll
            for (int i = 0; i < 4; i++) {
                float4 p4 = *(const float4*)&Ps[(ty*4 + i)*68 + jj0];
                p[i][0] = p4.x; p[i][1] = p4.y; p[i][2] = p4.z; p[i][3] = p4.w;
            }
#pragma unroll
            for (int q = 0; q < 4; q++) {
                float4 v4 = *(const float4*)&Vs[(jj0 + q)*68 + tx*4];
                float v[4] = {v4.x, v4.y, v4.z, v4.w};
#pragma unroll
                for (int i = 0; i < 4; i++)
#pragma unroll
                    for (int d = 0; d < 4; d++)
                        acc[i][d] = fmaf(p[i][q], v[d], acc[i][d]);
            }
        }
    }

#pragma unroll
    for (int off = 8; off > 0; off >>= 1)
#pragma unroll
        for (int i = 0; i < 4; i++)
            lpart[i] += __shfl_xor_sync(0xffffffffu, lpart[i], off);

    float* Og = g_O + ((size_t)b * SEQ + qt * 64) * DM + h * DH;
#pragma unroll
    for (int i = 0; i < 4; i++) {
        float inv = 1.f / lpart[i];
        float4 o = make_float4(acc[i][0]*inv, acc[i][1]*inv, acc[i][2]*inv, acc[i][3]*inv);
        *(float4*)(Og + (size_t)(ty*4 + i) * DM + tx*4) = o;
    }
}

extern "C" void kernel_launch(void* const* d_in, const int* in_sizes, int n_in,
                              void* d_out, int out_size) {
    const float* x    = (const float*)d_in[0];
    const float* Wq   = (const float*)d_in[1];
    const float* Wk   = (const float*)d_in[2];
    const float* Wv   = (const float*)d_in[3];
    const float* Wo   = (const float*)d_in[4];
    const float* logc = (const float*)d_in[5];
    const float* logb = (const float*)d_in[6];
    if (in_sizes[0] != NB * SEQ * DM) {
        const float* xf = nullptr; const float* ws[4] = {}; const float* sc[2] = {};
        int nw = 0, ns = 0;
        for (int i = 0; i < n_in; i++) {
            if (in_sizes[i] == NB * SEQ * DM)          xf = (const float*)d_in[i];
            else if (in_sizes[i] == DM * DM && nw < 4) ws[nw++] = (const float*)d_in[i];
            else if (in_sizes[i] == 1 && ns < 2)       sc[ns++] = (const float*)d_in[i];
        }
        if (xf && nw == 4 && ns == 2) {
            x = xf; Wq = ws[0]; Wk = ws[1]; Wv = ws[2]; Wo = ws[3];
            logc = sc[0]; logb = sc[1];
        }
    }
    float* out = (float*)d_out;

    size_t asmem = (size_t)(4*64*68 + 2*64) * sizeof(float);   // 70144 B
    cudaFuncSetAttribute(attn_kernel, cudaFuncAttributeMaxDynamicSharedMemorySize, (int)asmem);

    // ---- convert inputs to bf16 hi/lo ----
    cvt_kernel<<<(MROWS*DM/4 + 255)/256, 256>>>(x,  0, MROWS*DM);
    cvt_kernel<<<(DM*DM/4   + 255)/256, 256>>>(Wq, 1, DM*DM);
    cvt_kernel<<<(DM*DM/4   + 255)/256, 256>>>(Wk, 2, DM*DM);
    cvt_kernel<<<(DM*DM/4   + 255)/256, 256>>>(Wv, 3, DM*DM);
    cvt_kernel<<<(DM*DM/4   + 255)/256, 256>>>(Wo, 4, DM*DM);

    // ---- Q,K,V projections ----
    dim3 pgrid(DM / 128, MROWS / 128, 3);
    mma_gemm_kernel<0><<<pgrid, 256>>>(nullptr);

    // ---- attention ----
    dim3 agrid(SEQ / 64, NH, NB);
    attn_kernel<<<agrid, 256, asmem>>>(logc, logb);

    // ---- O conversion + output projection ----
    cvt_kernel<<<(MROWS*DM/4 + 255)/256, 256>>>(nullptr, 5, MROWS*DM);
    dim3 ogrid(DM / 128, MROWS / 128, 1);
    mma_gemm_kernel<1><<<ogrid, 256>>>(out);
}

// round 8
// speedup vs baseline: 2.4932x; 1.7231x over previous
#include <cuda_runtime.h>
#include <cuda_bf16.h>
#include <math_constants.h>
#include <cstdint>

#define SEQ 2048
#define DM  512
#define NB  2
#define NH  8
#define DH  64
#define MROWS (NB*SEQ)   // 4096

// split-bf16 activations (hi/lo), head-split layout [b][h][n][dh]
__device__ __align__(16) __nv_bfloat16 g_Qh[NB*NH*SEQ*DH], g_Ql[NB*NH*SEQ*DH];
__device__ __align__(16) __nv_bfloat16 g_Kh[NB*NH*SEQ*DH], g_Kl[NB*NH*SEQ*DH];
__device__ __align__(16) __nv_bfloat16 g_Vh[NB*NH*SEQ*DH], g_Vl[NB*NH*SEQ*DH];
// GEMM operands
__device__ __align__(16) __nv_bfloat16 g_xh[MROWS*DM], g_xl[MROWS*DM];
__device__ __align__(16) __nv_bfloat16 g_Wh[4*DM*DM],  g_Wl[4*DM*DM];
__device__ __align__(16) __nv_bfloat16 g_Oh[MROWS*DM], g_Ol[MROWS*DM];

// ---------------- warp-MMA helpers ----------------
__device__ __forceinline__ uint32_t smem_u32(const void* p) {
    uint32_t a;
    asm("{ .reg .u64 t; cvta.to.shared.u64 t, %1; cvt.u32.u64 %0, t; }" : "=r"(a) : "l"(p));
    return a;
}
__device__ __forceinline__ void ldm_x4(uint32_t* r, uint32_t addr) {
    asm volatile("ldmatrix.sync.aligned.m8n8.x4.shared.b16 {%0,%1,%2,%3}, [%4];"
                 : "=r"(r[0]), "=r"(r[1]), "=r"(r[2]), "=r"(r[3]) : "r"(addr));
}
__device__ __forceinline__ void ldm_x4_trans(uint32_t* r, uint32_t addr) {
    asm volatile("ldmatrix.sync.aligned.m8n8.x4.trans.shared.b16 {%0,%1,%2,%3}, [%4];"
                 : "=r"(r[0]), "=r"(r[1]), "=r"(r[2]), "=r"(r[3]) : "r"(addr));
}
__device__ __forceinline__ void mma_bf16(float* d, const uint32_t* a, const uint32_t* b) {
    asm volatile("mma.sync.aligned.m16n8k16.row.col.f32.bf16.bf16.f32 "
                 "{%0,%1,%2,%3}, {%4,%5,%6,%7}, {%8,%9}, {%0,%1,%2,%3};"
                 : "+f"(d[0]), "+f"(d[1]), "+f"(d[2]), "+f"(d[3])
                 : "r"(a[0]), "r"(a[1]), "r"(a[2]), "r"(a[3]), "r"(b[0]), "r"(b[1]));
}
// pack (a,b) into bf16x2 hi + residual-lo words
__device__ __forceinline__ void split2(float a, float b, uint32_t& h, uint32_t& l) {
    __nv_bfloat16 ha = __float2bfloat16(a), hb = __float2bfloat16(b);
    __nv_bfloat16 la = __float2bfloat16(a - __bfloat162float(ha));
    __nv_bfloat16 lb = __float2bfloat16(b - __bfloat162float(hb));
    __nv_bfloat162 H; H.x = ha; H.y = hb;
    __nv_bfloat162 L; L.x = la; L.y = lb;
    h = *(uint32_t*)&H; l = *(uint32_t*)&L;
}

// ---------------- fp32 -> bf16 (hi, lo) split conversion (x and weights) ----------------
__global__ void __launch_bounds__(256) cvt_kernel(const float* __restrict__ src,
                                                  int dst_sel, int n) {
    int i = (blockIdx.x * 256 + threadIdx.x) * 4;
    if (i >= n) return;
    __nv_bfloat16 *dh, *dl;
    if (dst_sel == 0) { dh = g_xh; dl = g_xl; }
    else { dh = g_Wh + (size_t)(dst_sel-1)*DM*DM; dl = g_Wl + (size_t)(dst_sel-1)*DM*DM; }
    float4 v = *(const float4*)(src + i);
    float vv[4] = {v.x, v.y, v.z, v.w};
#pragma unroll
    for (int k = 0; k < 4; k++) {
        __nv_bfloat16 h = __float2bfloat16(vv[k]);
        dh[i + k] = h;
        dl[i + k] = __float2bfloat16(vv[k] - __bfloat162float(h));
    }
}

// ---------------- split-bf16 GEMM via mma.sync ----------------
// MODE 0: A = g_xh/l, W = g_Wh/l + z*DM*DM -> write split-bf16 Q/K/V head-split
// MODE 1: A = g_Oh/l, W index 3 (Wo)       -> plain fp32 [m][j] out
#define ASTR 40

template<int MODE>
__global__ void __launch_bounds__(256) mma_gemm_kernel(float* __restrict__ outp) {
    __shared__ __align__(16) __nv_bfloat16 sAh[128*ASTR], sAl[128*ASTR];
    __shared__ __align__(16) __nv_bfloat16 sBh[128*ASTR], sBl[128*ASTR];

    const int t = threadIdx.x, lane = t & 31, w = t >> 5;
    const int wm = w & 3, wn = w >> 2;
    const int m0 = blockIdx.y * 128, j0 = blockIdx.x * 128;
    const int wsel = (MODE == 0) ? (int)blockIdx.z : 3;

    const __nv_bfloat16* Ahp = (MODE == 0) ? g_xh : g_Oh;
    const __nv_bfloat16* Alp = (MODE == 0) ? g_xl : g_Ol;
    const __nv_bfloat16* Whp = g_Wh + (size_t)wsel * DM * DM;
    const __nv_bfloat16* Wlp = g_Wl + (size_t)wsel * DM * DM;

    float acc[2][8][4];
#pragma unroll
    for (int mt = 0; mt < 2; mt++)
#pragma unroll
        for (int nt = 0; nt < 8; nt++)
#pragma unroll
            for (int e = 0; e < 4; e++) acc[mt][nt][e] = 0.f;

    const int arow = wm*32 + (lane & 15);
    const int boff = ((lane >> 4) & 1) * 8;
    const int brow = wn*64 + (lane & 7) + ((lane >> 4) & 1) * 8;
    const int bcol = ((lane >> 3) & 1) * 8;

    for (int s = 0; s < DM/32; s++) {
        __syncthreads();
#pragma unroll
        for (int p = 0; p < 2; p++) {
            int id = t + 256 * p;
            int r = id >> 2, cc = id & 3;
            const size_t ga = (size_t)(m0 + r) * DM + s*32 + cc*8;
            const size_t gb = (size_t)(j0 + r) * DM + s*32 + cc*8;
            *(uint4*)(sAh + r*ASTR + cc*8) = *(const uint4*)(Ahp + ga);
            *(uint4*)(sAl + r*ASTR + cc*8) = *(const uint4*)(Alp + ga);
            *(uint4*)(sBh + r*ASTR + cc*8) = *(const uint4*)(Whp + gb);
            *(uint4*)(sBl + r*ASTR + cc*8) = *(const uint4*)(Wlp + gb);
        }
        __syncthreads();

#pragma unroll
        for (int ks = 0; ks < 2; ks++) {
            uint32_t ah[2][4], al[2][4];
#pragma unroll
            for (int mt = 0; mt < 2; mt++) {
                ldm_x4(ah[mt], smem_u32(&sAh[(arow + mt*16)*ASTR + ks*16 + boff]));
                ldm_x4(al[mt], smem_u32(&sAl[(arow + mt*16)*ASTR + ks*16 + boff]));
            }
            uint32_t bh[8][2], bl[8][2];
#pragma unroll
            for (int pr = 0; pr < 4; pr++) {
                uint32_t r4[4];
                ldm_x4(r4, smem_u32(&sBh[(brow + pr*16)*ASTR + ks*16 + bcol]));
                bh[2*pr][0] = r4[0]; bh[2*pr][1] = r4[1];
                bh[2*pr+1][0] = r4[2]; bh[2*pr+1][1] = r4[3];
                ldm_x4(r4, smem_u32(&sBl[(brow + pr*16)*ASTR + ks*16 + bcol]));
                bl[2*pr][0] = r4[0]; bl[2*pr][1] = r4[1];
                bl[2*pr+1][0] = r4[2]; bl[2*pr+1][1] = r4[3];
            }
#pragma unroll
            for (int mt = 0; mt < 2; mt++)
#pragma unroll
                for (int nt = 0; nt < 8; nt++) {
                    mma_bf16(acc[mt][nt], ah[mt], bh[nt]);
                    mma_bf16(acc[mt][nt], ah[mt], bl[nt]);
                    mma_bf16(acc[mt][nt], al[mt], bh[nt]);
                }
        }
    }

    const int gid = lane >> 2, tig = lane & 3;
#pragma unroll
    for (int mt = 0; mt < 2; mt++) {
#pragma unroll
        for (int nt = 0; nt < 8; nt++) {
            const int mrow = m0 + wm*32 + mt*16 + gid;
            const int jcol = j0 + wn*64 + nt*8 + tig*2;
            if (MODE == 1) {
                *(float2*)(outp + (size_t)mrow * DM + jcol)     = make_float2(acc[mt][nt][0], acc[mt][nt][1]);
                *(float2*)(outp + (size_t)(mrow+8) * DM + jcol) = make_float2(acc[mt][nt][2], acc[mt][nt][3]);
            } else {
                __nv_bfloat16* dsh = (blockIdx.z == 0) ? g_Qh : (blockIdx.z == 1) ? g_Kh : g_Vh;
                __nv_bfloat16* dsl = (blockIdx.z == 0) ? g_Ql : (blockIdx.z == 1) ? g_Kl : g_Vl;
                const int hh = jcol >> 6, d = jcol & (DH-1);
                const int b0r = mrow >> 11, n0r = mrow & (SEQ-1);
                const size_t base = ((size_t)(b0r*NH + hh)*SEQ + n0r)*DH + d;
                uint32_t ph_, pl_;
                split2(acc[mt][nt][0], acc[mt][nt][1], ph_, pl_);
                *(uint32_t*)(dsh + base) = ph_;
                *(uint32_t*)(dsl + base) = pl_;
                split2(acc[mt][nt][2], acc[mt][nt][3], ph_, pl_);
                *(uint32_t*)(dsh + base + 8*DH) = ph_;
                *(uint32_t*)(dsl + base + 8*DH) = pl_;
            }
        }
    }
}

// ---------------- mma.sync hyperbolic flash attention ----------------
// CTA = 128 threads (4 warps), 64-query tile; warp w owns rows w*16..w*16+15.
#define KSTR 72

__global__ void __launch_bounds__(128) attn_mma_kernel(const float* __restrict__ p_logc,
                                                       const float* __restrict__ p_logb) {
    extern __shared__ __align__(16) char smraw[];
    __nv_bfloat16* Qh = (__nv_bfloat16*)smraw;
    __nv_bfloat16* Ql = Qh + 64*KSTR;
    __nv_bfloat16* Kh = Ql + 64*KSTR;
    __nv_bfloat16* Kl = Kh + 64*KSTR;
    __nv_bfloat16* Vh = Kl + 64*KSTR;
    __nv_bfloat16* Vl = Vh + 64*KSTR;
    float* qn = (float*)(Vl + 64*KSTR);   // [64]
    float* kn = qn + 64;                  // [64]

    const int t = threadIdx.x, lane = t & 31, w = t >> 5;
    const int qt = (int)(gridDim.x - 1 - blockIdx.x);   // heavy blocks first
    const int h = blockIdx.y, b = blockIdx.z;
    const int bh = b*NH + h;

    const float c    = log1pf(__expf(*p_logc));
    const float beta = log1pf(__expf(*p_logb)) + 0.5f;

    const size_t qoff = ((size_t)bh*SEQ + qt*64) * DH;
#pragma unroll
    for (int p = 0; p < 4; p++) {
        int id = t + 128*p;
        int r = id >> 3, cc = id & 7;
        *(uint4*)&Qh[r*KSTR + cc*8] = *(const uint4*)(g_Qh + qoff + r*64 + cc*8);
        *(uint4*)&Ql[r*KSTR + cc*8] = *(const uint4*)(g_Ql + qoff + r*64 + cc*8);
    }
    __syncthreads();
    {
        int r = t >> 1, half = t & 1;
        float s = 0.f;
#pragma unroll 8
        for (int d = half*32; d < half*32 + 32; d++) {
            float v = __bfloat162float(Qh[r*KSTR + d]) + __bfloat162float(Ql[r*KSTR + d]);
            s = fmaf(v, v, s);
        }
        s += __shfl_xor_sync(0xffffffffu, s, 1);
        if (!half) qn[r] = s;
    }

    const int arow  = w*16 + (lane & 15);
    const int acsel = ((lane >> 4) & 1) * 8;
    const int brow  = (lane & 7) + ((lane >> 4) & 1) * 8;
    const int bcol  = ((lane >> 3) & 1) * 8;
    const int gid   = lane >> 2, tig = lane & 3;

    float accO[8][4];
#pragma unroll
    for (int nt = 0; nt < 8; nt++)
#pragma unroll
        for (int e = 0; e < 4; e++) accO[nt][e] = 0.f;
    float m0 = -CUDART_INF_F, m1 = -CUDART_INF_F, l0 = 0.f, l1 = 0.f;

    for (int kt = 0; kt <= qt; kt++) {
        __syncthreads();
        const size_t koff = ((size_t)bh*SEQ + kt*64) * DH;
#pragma unroll
        for (int p = 0; p < 4; p++) {
            int id = t + 128*p;
            int r = id >> 3, cc = id & 7;
            *(uint4*)&Kh[r*KSTR + cc*8] = *(const uint4*)(g_Kh + koff + r*64 + cc*8);
            *(uint4*)&Kl[r*KSTR + cc*8] = *(const uint4*)(g_Kl + koff + r*64 + cc*8);
            *(uint4*)&Vh[r*KSTR + cc*8] = *(const uint4*)(g_Vh + koff + r*64 + cc*8);
            *(uint4*)&Vl[r*KSTR + cc*8] = *(const uint4*)(g_Vl + koff + r*64 + cc*8);
        }
        __syncthreads();
        {
            int r = t >> 1, half = t & 1;
            float s = 0.f;
#pragma unroll 8
            for (int d = half*32; d < half*32 + 32; d++) {
                float v = __bfloat162float(Kh[r*KSTR + d]) + __bfloat162float(Kl[r*KSTR + d]);
                s = fmaf(v, v, s);
            }
            s += __shfl_xor_sync(0xffffffffu, s, 1);
            if (!half) kn[r] = s;
        }
        __syncthreads();

        // ---- S = Q K^T (split bf16: hh + hl + lh) ----
        float accS[8][4];
#pragma unroll
        for (int nt = 0; nt < 8; nt++)
#pragma unroll
            for (int e = 0; e < 4; e++) accS[nt][e] = 0.f;
#pragma unroll
        for (int ks = 0; ks < 4; ks++) {
            uint32_t ah[4], al[4];
            ldm_x4(ah, smem_u32(&Qh[arow*KSTR + ks*16 + acsel]));
            ldm_x4(al, smem_u32(&Ql[arow*KSTR + ks*16 + acsel]));
            uint32_t kbh[8][2], kbl[8][2];
#pragma unroll
            for (int pr = 0; pr < 4; pr++) {
                uint32_t r4[4];
                ldm_x4(r4, smem_u32(&Kh[(brow + pr*16)*KSTR + ks*16 + bcol]));
                kbh[2*pr][0] = r4[0]; kbh[2*pr][1] = r4[1];
                kbh[2*pr+1][0] = r4[2]; kbh[2*pr+1][1] = r4[3];
                ldm_x4(r4, smem_u32(&Kl[(brow + pr*16)*KSTR + ks*16 + bcol]));
                kbl[2*pr][0] = r4[0]; kbl[2*pr][1] = r4[1];
                kbl[2*pr+1][0] = r4[2]; kbl[2*pr+1][1] = r4[3];
            }
#pragma unroll
            for (int nt = 0; nt < 8; nt++) {
                mma_bf16(accS[nt], ah, kbh[nt]);
                mma_bf16(accS[nt], ah, kbl[nt]);
                mma_bf16(accS[nt], al, kbh[nt]);
            }
        }

        // ---- scores + online-max softmax ----
        const float qn0 = qn[w*16 + gid], qn1 = qn[w*16 + gid + 8];
        const int grow0 = qt*64 + w*16 + gid, grow1 = grow0 + 8;
        float rmax0 = -CUDART_INF_F, rmax1 = -CUDART_INF_F;
#pragma unroll
        for (int nt = 0; nt < 8; nt++) {
            const int lc = nt*8 + tig*2;
            const int gc0 = kt*64 + lc, gc1 = gc0 + 1;
            const float kn0 = kn[lc], kn1 = kn[lc + 1];
            float sv[4] = {accS[nt][0], accS[nt][1], accS[nt][2], accS[nt][3]};
            float qq[4] = {qn0, qn0, qn1, qn1};
            float kk[4] = {kn0, kn1, kn0, kn1};
            bool  ok[4] = {gc0 <= grow0, gc1 <= grow0, gc0 <= grow1, gc1 <= grow1};
#pragma unroll
            for (int e = 0; e < 4; e++) {
                float a    = qq[e] + kk[e];
                float diff = fmaxf(fmaf(-2.f, sv[e], a), 0.f) + 1e-8f;
                float prod = diff * fmaf(c, a, 1.f);
                float sc   = -beta * (prod * rsqrtf(prod));
                accS[nt][e] = ok[e] ? sc : -CUDART_INF_F;
            }
            rmax0 = fmaxf(rmax0, fmaxf(accS[nt][0], accS[nt][1]));
            rmax1 = fmaxf(rmax1, fmaxf(accS[nt][2], accS[nt][3]));
        }
        rmax0 = fmaxf(rmax0, __shfl_xor_sync(0xffffffffu, rmax0, 1));
        rmax0 = fmaxf(rmax0, __shfl_xor_sync(0xffffffffu, rmax0, 2));
        rmax1 = fmaxf(rmax1, __shfl_xor_sync(0xffffffffu, rmax1, 1));
        rmax1 = fmaxf(rmax1, __shfl_xor_sync(0xffffffffu, rmax1, 2));

        const float mn0 = fmaxf(m0, rmax0), mn1 = fmaxf(m1, rmax1);
        const float sc0 = __expf(m0 - mn0), sc1 = __expf(m1 - mn1);
        m0 = mn0; m1 = mn1;
        float rs0 = 0.f, rs1 = 0.f;
#pragma unroll
        for (int nt = 0; nt < 8; nt++) {
            accO[nt][0] *= sc0; accO[nt][1] *= sc0;
            accO[nt][2] *= sc1; accO[nt][3] *= sc1;
            float w0 = __expf(accS[nt][0] - mn0);
            float w1 = __expf(accS[nt][1] - mn0);
            float w2 = __expf(accS[nt][2] - mn1);
            float w3 = __expf(accS[nt][3] - mn1);
            accS[nt][0] = w0; accS[nt][1] = w1; accS[nt][2] = w2; accS[nt][3] = w3;
            rs0 += w0 + w1; rs1 += w2 + w3;
        }
        rs0 += __shfl_xor_sync(0xffffffffu, rs0, 1);
        rs0 += __shfl_xor_sync(0xffffffffu, rs0, 2);
        rs1 += __shfl_xor_sync(0xffffffffu, rs1, 1);
        rs1 += __shfl_xor_sync(0xffffffffu, rs1, 2);
        l0 = l0*sc0 + rs0; l1 = l1*sc1 + rs1;

        // ---- O += P V (P packed from S accumulators; V B-frags via trans ldmatrix) ----
        const int vrow = ((lane >> 3) & 1) * 8 + (lane & 7);   // + ks*16 -> key row
        const int vcol = ((lane >> 4) & 1) * 8;                // + pr*16 -> d col
#pragma unroll
        for (int ks = 0; ks < 4; ks++) {
            uint32_t ph[4], pl[4];
            split2(accS[2*ks][0],   accS[2*ks][1],   ph[0], pl[0]);
            split2(accS[2*ks][2],   accS[2*ks][3],   ph[1], pl[1]);
            split2(accS[2*ks+1][0], accS[2*ks+1][1], ph[2], pl[2]);
            split2(accS[2*ks+1][2], accS[2*ks+1][3], ph[3], pl[3]);
            uint32_t vbh[8][2], vbl[8][2];
#pragma unroll
            for (int pr = 0; pr < 4; pr++) {
                uint32_t r4[4];
                ldm_x4_trans(r4, smem_u32(&Vh[(ks*16 + vrow)*KSTR + pr*16 + vcol]));
                vbh[2*pr][0] = r4[0]; vbh[2*pr][1] = r4[1];
                vbh[2*pr+1][0] = r4[2]; vbh[2*pr+1][1] = r4[3];
                ldm_x4_trans(r4, smem_u32(&Vl[(ks*16 + vrow)*KSTR + pr*16 + vcol]));
                vbl[2*pr][0] = r4[0]; vbl[2*pr][1] = r4[1];
                vbl[2*pr+1][0] = r4[2]; vbl[2*pr+1][1] = r4[3];
            }
#pragma unroll
            for (int nt = 0; nt < 8; nt++) {
                mma_bf16(accO[nt], ph, vbh[nt]);
                mma_bf16(accO[nt], ph, vbl[nt]);
                mma_bf16(accO[nt], pl, vbh[nt]);
            }
        }
    }

    // ---- normalize + write O as split bf16, layout [b][n][h*64+d] ----
    const float inv0 = 1.f / l0, inv1 = 1.f / l1;
    const int row0 = qt*64 + w*16 + gid;
    const size_t base0 = ((size_t)b*SEQ + row0)*DM + h*DH;
    const size_t base1 = base0 + (size_t)8*DM;
#pragma unroll
    for (int nt = 0; nt < 8; nt++) {
        const int d = nt*8 + tig*2;
        uint32_t hh, ll;
        split2(accO[nt][0]*inv0, accO[nt][1]*inv0, hh, ll);
        *(uint32_t*)(g_Oh + base0 + d) = hh;
        *(uint32_t*)(g_Ol + base0 + d) = ll;
        split2(accO[nt][2]*inv1, accO[nt][3]*inv1, hh, ll);
        *(uint32_t*)(g_Oh + base1 + d) = hh;
        *(uint32_t*)(g_Ol + base1 + d) = ll;
    }
}

extern "C" void kernel_launch(void* const* d_in, const int* in_sizes, int n_in,
                              void* d_out, int out_size) {
    const float* x    = (const float*)d_in[0];
    const float* Wq   = (const float*)d_in[1];
    const float* Wk   = (const float*)d_in[2];
    const float* Wv   = (const float*)d_in[3];
    const float* Wo   = (const float*)d_in[4];
    const float* logc = (const float*)d_in[5];
    const float* logb = (const float*)d_in[6];
    if (in_sizes[0] != NB * SEQ * DM) {
        const float* xf = nullptr; const float* ws[4] = {}; const float* sc[2] = {};
        int nw = 0, ns = 0;
        for (int i = 0; i < n_in; i++) {
            if (in_sizes[i] == NB * SEQ * DM)          xf = (const float*)d_in[i];
            else if (in_sizes[i] == DM * DM && nw < 4) ws[nw++] = (const float*)d_in[i];
            else if (in_sizes[i] == 1 && ns < 2)       sc[ns++] = (const float*)d_in[i];
        }
        if (xf && nw == 4 && ns == 2) {
            x = xf; Wq = ws[0]; Wk = ws[1]; Wv = ws[2]; Wo = ws[3];
            logc = sc[0]; logb = sc[1];
        }
    }
    float* out = (float*)d_out;

    const int attn_smem = (6*64*KSTR)*2 + 2*64*4;   // 55808 B
    cudaFuncSetAttribute(attn_mma_kernel, cudaFuncAttributeMaxDynamicSharedMemorySize, attn_smem);

    cvt_kernel<<<(MROWS*DM/4 + 255)/256, 256>>>(x,  0, MROWS*DM);
    cvt_kernel<<<(DM*DM/4   + 255)/256, 256>>>(Wq, 1, DM*DM);
    cvt_kernel<<<(DM*DM/4   + 255)/256, 256>>>(Wk, 2, DM*DM);
    cvt_kernel<<<(DM*DM/4   + 255)/256, 256>>>(Wv, 3, DM*DM);
    cvt_kernel<<<(DM*DM/4   + 255)/256, 256>>>(Wo, 4, DM*DM);

    dim3 pgrid(DM / 128, MROWS / 128, 3);
    mma_gemm_kernel<0><<<pgrid, 256>>>(nullptr);

    dim3 agrid(SEQ / 64, NH, NB);
    attn_mma_kernel<<<agrid, 128, attn_smem>>>(logc, logb);

    dim3 ogrid(DM / 128, MROWS / 128, 1);
    mma_gemm_kernel<1><<<ogrid, 256>>>(out);
}

// round 9
// speedup vs baseline: 2.8957x; 1.1614x over previous
#include <cuda_runtime.h>
#include <cuda_bf16.h>
#include <cuda_fp16.h>
#include <math_constants.h>
#include <cstdint>

#define SEQ 2048
#define DM  512
#define NB  2
#define NH  8
#define DH  64
#define MROWS (NB*SEQ)   // 4096

// split activations, head-split layout [b][h][n][dh]
__device__ __align__(16) __nv_bfloat16 g_Qh[NB*NH*SEQ*DH], g_Ql[NB*NH*SEQ*DH];
__device__ __align__(16) __nv_bfloat16 g_Kh[NB*NH*SEQ*DH], g_Kl[NB*NH*SEQ*DH];
__device__ __align__(16) __half       g_Vh[NB*NH*SEQ*DH], g_Vl[NB*NH*SEQ*DH];
__device__ __align__(16) float        g_qn[NB*NH*SEQ], g_kn[NB*NH*SEQ];
// GEMM operands
__device__ __align__(16) __nv_bfloat16 g_xh[MROWS*DM], g_xl[MROWS*DM];
__device__ __align__(16) __nv_bfloat16 g_Wh[4*DM*DM],  g_Wl[4*DM*DM];
__device__ __align__(16) __nv_bfloat16 g_Oh[MROWS*DM], g_Ol[MROWS*DM];

// ---------------- warp-MMA helpers ----------------
__device__ __forceinline__ uint32_t smem_u32(const void* p) {
    uint32_t a;
    asm("{ .reg .u64 t; cvta.to.shared.u64 t, %1; cvt.u32.u64 %0, t; }" : "=r"(a) : "l"(p));
    return a;
}
__device__ __forceinline__ void ldm_x4(uint32_t* r, uint32_t addr) {
    asm volatile("ldmatrix.sync.aligned.m8n8.x4.shared.b16 {%0,%1,%2,%3}, [%4];"
                 : "=r"(r[0]), "=r"(r[1]), "=r"(r[2]), "=r"(r[3]) : "r"(addr));
}
__device__ __forceinline__ void ldm_x4_trans(uint32_t* r, uint32_t addr) {
    asm volatile("ldmatrix.sync.aligned.m8n8.x4.trans.shared.b16 {%0,%1,%2,%3}, [%4];"
                 : "=r"(r[0]), "=r"(r[1]), "=r"(r[2]), "=r"(r[3]) : "r"(addr));
}
__device__ __forceinline__ void mma_bf16(float* d, const uint32_t* a, const uint32_t* b) {
    asm volatile("mma.sync.aligned.m16n8k16.row.col.f32.bf16.bf16.f32 "
                 "{%0,%1,%2,%3}, {%4,%5,%6,%7}, {%8,%9}, {%0,%1,%2,%3};"
                 : "+f"(d[0]), "+f"(d[1]), "+f"(d[2]), "+f"(d[3])
                 : "r"(a[0]), "r"(a[1]), "r"(a[2]), "r"(a[3]), "r"(b[0]), "r"(b[1]));
}
__device__ __forceinline__ void mma_f16(float* d, const uint32_t* a, const uint32_t* b) {
    asm volatile("mma.sync.aligned.m16n8k16.row.col.f32.f16.f16.f32 "
                 "{%0,%1,%2,%3}, {%4,%5,%6,%7}, {%8,%9}, {%0,%1,%2,%3};"
                 : "+f"(d[0]), "+f"(d[1]), "+f"(d[2]), "+f"(d[3])
                 : "r"(a[0]), "r"(a[1]), "r"(a[2]), "r"(a[3]), "r"(b[0]), "r"(b[1]));
}
__device__ __forceinline__ void split2(float a, float b, uint32_t& h, uint32_t& l) {
    __nv_bfloat16 ha = __float2bfloat16(a), hb = __float2bfloat16(b);
    __nv_bfloat16 la = __float2bfloat16(a - __bfloat162float(ha));
    __nv_bfloat16 lb = __float2bfloat16(b - __bfloat162float(hb));
    __nv_bfloat162 H; H.x = ha; H.y = hb;
    __nv_bfloat162 L; L.x = la; L.y = lb;
    h = *(uint32_t*)&H; l = *(uint32_t*)&L;
}
__device__ __forceinline__ void split2h(float a, float b, uint32_t& h, uint32_t& l) {
    __half ha = __float2half_rn(a), hb = __float2half_rn(b);
    __half la = __float2half_rn(a - __half2float(ha));
    __half lb = __float2half_rn(b - __half2float(hb));
    __half2 H; H.x = ha; H.y = hb;
    __half2 L; L.x = la; L.y = lb;
    h = *(uint32_t*)&H; l = *(uint32_t*)&L;
}
__device__ __forceinline__ uint32_t packh2(float a, float b) {
    __half2 h = __floats2half2_rn(a, b);
    return *(uint32_t*)&h;
}

// ---------------- conversions ----------------
__global__ void __launch_bounds__(256) cvt_x_kernel(const float* __restrict__ src, int n) {
    int i = (blockIdx.x * 256 + threadIdx.x) * 4;
    if (i >= n) return;
    float4 v = *(const float4*)(src + i);
    float vv[4] = {v.x, v.y, v.z, v.w};
#pragma unroll
    for (int k = 0; k < 4; k++) {
        __nv_bfloat16 h = __float2bfloat16(vv[k]);
        g_xh[i + k] = h;
        g_xl[i + k] = __float2bfloat16(vv[k] - __bfloat162float(h));
    }
}
__global__ void __launch_bounds__(256) cvt_w_kernel(const float* __restrict__ w0,
                                                    const float* __restrict__ w1,
                                                    const float* __restrict__ w2,
                                                    const float* __restrict__ w3) {
    const int z = blockIdx.y;
    const float* src = (z == 0) ? w0 : (z == 1) ? w1 : (z == 2) ? w2 : w3;
    int i = (blockIdx.x * 256 + threadIdx.x) * 4;
    __nv_bfloat16* dh = g_Wh + (size_t)z * DM * DM;
    __nv_bfloat16* dl = g_Wl + (size_t)z * DM * DM;
    float4 v = *(const float4*)(src + i);
    float vv[4] = {v.x, v.y, v.z, v.w};
#pragma unroll
    for (int k = 0; k < 4; k++) {
        __nv_bfloat16 h = __float2bfloat16(vv[k]);
        dh[i + k] = h;
        dl[i + k] = __float2bfloat16(vv[k] - __bfloat162float(h));
    }
}

// ---------------- split-bf16 GEMM via mma.sync ----------------
// MODE 0: A = g_xh/l, W = g_Wh/l + z*DM*DM -> z=0/1: split-bf16 Q/K + row norms; z=2: split-fp16 V
// MODE 1: A = g_Oh/l, W index 3 (Wo)       -> plain fp32 [m][j] out
#define ASTR 40

template<int MODE>
__global__ void __launch_bounds__(256) mma_gemm_kernel(float* __restrict__ outp) {
    __shared__ __align__(16) __nv_bfloat16 sAh[128*ASTR], sAl[128*ASTR];
    __shared__ __align__(16) __nv_bfloat16 sBh[128*ASTR], sBl[128*ASTR];

    const int t = threadIdx.x, lane = t & 31, w = t >> 5;
    const int wm = w & 3, wn = w >> 2;
    const int m0 = blockIdx.y * 128, j0 = blockIdx.x * 128;
    const int wsel = (MODE == 0) ? (int)blockIdx.z : 3;

    const __nv_bfloat16* Ahp = (MODE == 0) ? g_xh : g_Oh;
    const __nv_bfloat16* Alp = (MODE == 0) ? g_xl : g_Ol;
    const __nv_bfloat16* Whp = g_Wh + (size_t)wsel * DM * DM;
    const __nv_bfloat16* Wlp = g_Wl + (size_t)wsel * DM * DM;

    float acc[2][8][4];
#pragma unroll
    for (int mt = 0; mt < 2; mt++)
#pragma unroll
        for (int nt = 0; nt < 8; nt++)
#pragma unroll
            for (int e = 0; e < 4; e++) acc[mt][nt][e] = 0.f;

    const int arow = wm*32 + (lane & 15);
    const int boff = ((lane >> 4) & 1) * 8;
    const int brow = wn*64 + (lane & 7) + ((lane >> 4) & 1) * 8;
    const int bcol = ((lane >> 3) & 1) * 8;

    for (int s = 0; s < DM/32; s++) {
        __syncthreads();
#pragma unroll
        for (int p = 0; p < 2; p++) {
            int id = t + 256 * p;
            int r = id >> 2, cc = id & 3;
            const size_t ga = (size_t)(m0 + r) * DM + s*32 + cc*8;
            const size_t gb = (size_t)(j0 + r) * DM + s*32 + cc*8;
            *(uint4*)(sAh + r*ASTR + cc*8) = *(const uint4*)(Ahp + ga);
            *(uint4*)(sAl + r*ASTR + cc*8) = *(const uint4*)(Alp + ga);
            *(uint4*)(sBh + r*ASTR + cc*8) = *(const uint4*)(Whp + gb);
            *(uint4*)(sBl + r*ASTR + cc*8) = *(const uint4*)(Wlp + gb);
        }
        __syncthreads();

#pragma unroll
        for (int ks = 0; ks < 2; ks++) {
            uint32_t ah[2][4], al[2][4];
#pragma unroll
            for (int mt = 0; mt < 2; mt++) {
                ldm_x4(ah[mt], smem_u32(&sAh[(arow + mt*16)*ASTR + ks*16 + boff]));
                ldm_x4(al[mt], smem_u32(&sAl[(arow + mt*16)*ASTR + ks*16 + boff]));
            }
            uint32_t bh[8][2], bl[8][2];
#pragma unroll
            for (int pr = 0; pr < 4; pr++) {
                uint32_t r4[4];
                ldm_x4(r4, smem_u32(&sBh[(brow + pr*16)*ASTR + ks*16 + bcol]));
                bh[2*pr][0] = r4[0]; bh[2*pr][1] = r4[1];
                bh[2*pr+1][0] = r4[2]; bh[2*pr+1][1] = r4[3];
                ldm_x4(r4, smem_u32(&sBl[(brow + pr*16)*ASTR + ks*16 + bcol]));
                bl[2*pr][0] = r4[0]; bl[2*pr][1] = r4[1];
                bl[2*pr+1][0] = r4[2]; bl[2*pr+1][1] = r4[3];
            }
#pragma unroll
            for (int mt = 0; mt < 2; mt++)
#pragma unroll
                for (int nt = 0; nt < 8; nt++) {
                    mma_bf16(acc[mt][nt], ah[mt], bh[nt]);
                    mma_bf16(acc[mt][nt], ah[mt], bl[nt]);
                    mma_bf16(acc[mt][nt], al[mt], bh[nt]);
                }
        }
    }

    const int gid = lane >> 2, tig = lane & 3;
#pragma unroll
    for (int mt = 0; mt < 2; mt++) {
#pragma unroll
        for (int nt = 0; nt < 8; nt++) {
            const int mrow = m0 + wm*32 + mt*16 + gid;
            const int jcol = j0 + wn*64 + nt*8 + tig*2;
            if (MODE == 1) {
                *(float2*)(outp + (size_t)mrow * DM + jcol)     = make_float2(acc[mt][nt][0], acc[mt][nt][1]);
                *(float2*)(outp + (size_t)(mrow+8) * DM + jcol) = make_float2(acc[mt][nt][2], acc[mt][nt][3]);
            } else {
                const int hh = jcol >> 6, d = jcol & (DH-1);
                const int b0r = mrow >> 11, n0r = mrow & (SEQ-1);
                const size_t base = ((size_t)(b0r*NH + hh)*SEQ + n0r)*DH + d;
                uint32_t ph_, pl_;
                if (blockIdx.z == 2) {          // V: split fp16
                    split2h(acc[mt][nt][0], acc[mt][nt][1], ph_, pl_);
                    *(uint32_t*)(g_Vh + base) = ph_;
                    *(uint32_t*)(g_Vl + base) = pl_;
                    split2h(acc[mt][nt][2], acc[mt][nt][3], ph_, pl_);
                    *(uint32_t*)(g_Vh + base + 8*DH) = ph_;
                    *(uint32_t*)(g_Vl + base + 8*DH) = pl_;
                } else {                         // Q/K: split bf16
                    __nv_bfloat16* dsh = (blockIdx.z == 0) ? g_Qh : g_Kh;
                    __nv_bfloat16* dsl = (blockIdx.z == 0) ? g_Ql : g_Kl;
                    split2(acc[mt][nt][0], acc[mt][nt][1], ph_, pl_);
                    *(uint32_t*)(dsh + base) = ph_;
                    *(uint32_t*)(dsl + base) = pl_;
                    split2(acc[mt][nt][2], acc[mt][nt][3], ph_, pl_);
                    *(uint32_t*)(dsh + base + 8*DH) = ph_;
                    *(uint32_t*)(dsl + base + 8*DH) = pl_;
                }
            }
        }
    }

    // ---- exact fp32 row norms for Q (z=0) and K (z=1): warp covers one full head ----
    if (MODE == 0 && blockIdx.z < 2) {
        float* np = (blockIdx.z == 0) ? g_qn : g_kn;
        const int hh = (j0 + wn*64) >> 6;
#pragma unroll
        for (int mt = 0; mt < 2; mt++) {
            float s0 = 0.f, s1 = 0.f;
#pragma unroll
            for (int nt = 0; nt < 8; nt++) {
                s0 = fmaf(acc[mt][nt][0], acc[mt][nt][0], fmaf(acc[mt][nt][1], acc[mt][nt][1], s0));
                s1 = fmaf(acc[mt][nt][2], acc[mt][nt][2], fmaf(acc[mt][nt][3], acc[mt][nt][3], s1));
            }
            s0 += __shfl_xor_sync(0xffffffffu, s0, 1);
            s0 += __shfl_xor_sync(0xffffffffu, s0, 2);
            s1 += __shfl_xor_sync(0xffffffffu, s1, 1);
            s1 += __shfl_xor_sync(0xffffffffu, s1, 2);
            if (tig == 0) {
                const int mrow = m0 + wm*32 + mt*16 + gid;
                const int b0r = mrow >> 11, n0r = mrow & (SEQ-1);
                np[(size_t)(b0r*NH + hh)*SEQ + n0r]     = s0;
                np[(size_t)(b0r*NH + hh)*SEQ + n0r + 8] = s1;
            }
        }
    }
}

// ---------------- mma.sync hyperbolic flash attention ----------------
#define KSTR 72

__global__ void __launch_bounds__(128) attn_mma_kernel(const float* __restrict__ p_logc,
                                                       const float* __restrict__ p_logb) {
    extern __shared__ __align__(16) char smraw[];
    __nv_bfloat16* Qh = (__nv_bfloat16*)smraw;
    __nv_bfloat16* Ql = Qh + 64*KSTR;
    __nv_bfloat16* Kh = Ql + 64*KSTR;
    __nv_bfloat16* Kl = Kh + 64*KSTR;
    __half*        Vh = (__half*)(Kl + 64*KSTR);
    __half*        Vl = Vh + 64*KSTR;
    float*         kn = (float*)(Vl + 64*KSTR);   // [64]

    const int t = threadIdx.x, lane = t & 31, w = t >> 5;
    const int qt = (int)(gridDim.x - 1 - blockIdx.x);   // heavy blocks first
    const int h = blockIdx.y, b = blockIdx.z;
    const int bh = b*NH + h;

    const float c    = log1pf(__expf(*p_logc));
    const float beta = log1pf(__expf(*p_logb)) + 0.5f;

    const int gid = lane >> 2, tig = lane & 3;
    const size_t qoff = ((size_t)bh*SEQ + qt*64) * DH;
#pragma unroll
    for (int p = 0; p < 4; p++) {
        int id = t + 128*p;
        int r = id >> 3, cc = id & 7;
        *(uint4*)&Qh[r*KSTR + cc*8] = *(const uint4*)(g_Qh + qoff + r*64 + cc*8);
        *(uint4*)&Ql[r*KSTR + cc*8] = *(const uint4*)(g_Ql + qoff + r*64 + cc*8);
    }
    const float qn0 = g_qn[(size_t)bh*SEQ + qt*64 + w*16 + gid];
    const float qn1 = g_qn[(size_t)bh*SEQ + qt*64 + w*16 + gid + 8];

    const int arow  = w*16 + (lane & 15);
    const int acsel = ((lane >> 4) & 1) * 8;
    const int brow  = (lane & 7) + ((lane >> 4) & 1) * 8;
    const int bcol  = ((lane >> 3) & 1) * 8;

    float accO[8][4];
#pragma unroll
    for (int nt = 0; nt < 8; nt++)
#pragma unroll
        for (int e = 0; e < 4; e++) accO[nt][e] = 0.f;
    float m0 = -CUDART_INF_F, m1 = -CUDART_INF_F, l0 = 0.f, l1 = 0.f;

    for (int kt = 0; kt <= qt; kt++) {
        __syncthreads();
        const size_t koff = ((size_t)bh*SEQ + kt*64) * DH;
#pragma unroll
        for (int p = 0; p < 4; p++) {
            int id = t + 128*p;
            int r = id >> 3, cc = id & 7;
            *(uint4*)&Kh[r*KSTR + cc*8] = *(const uint4*)(g_Kh + koff + r*64 + cc*8);
            *(uint4*)&Kl[r*KSTR + cc*8] = *(const uint4*)(g_Kl + koff + r*64 + cc*8);
            *(uint4*)&Vh[r*KSTR + cc*8] = *(const uint4*)(g_Vh + koff + r*64 + cc*8);
            *(uint4*)&Vl[r*KSTR + cc*8] = *(const uint4*)(g_Vl + koff + r*64 + cc*8);
        }
        if (t < 64) kn[t] = g_kn[(size_t)bh*SEQ + kt*64 + t];
        __syncthreads();

        // ---- S = Q K^T (split bf16: hh + hl + lh) ----
        float accS[8][4];
#pragma unroll
        for (int nt = 0; nt < 8; nt++)
#pragma unroll
            for (int e = 0; e < 4; e++) accS[nt][e] = 0.f;
#pragma unroll
        for (int ks = 0; ks < 4; ks++) {
            uint32_t ah[4], al[4];
            ldm_x4(ah, smem_u32(&Qh[arow*KSTR + ks*16 + acsel]));
            ldm_x4(al, smem_u32(&Ql[arow*KSTR + ks*16 + acsel]));
            uint32_t kbh[8][2], kbl[8][2];
#pragma unroll
            for (int pr = 0; pr < 4; pr++) {
                uint32_t r4[4];
                ldm_x4(r4, smem_u32(&Kh[(brow + pr*16)*KSTR + ks*16 + bcol]));
                kbh[2*pr][0] = r4[0]; kbh[2*pr][1] = r4[1];
                kbh[2*pr+1][0] = r4[2]; kbh[2*pr+1][1] = r4[3];
                ldm_x4(r4, smem_u32(&Kl[(brow + pr*16)*KSTR + ks*16 + bcol]));
                kbl[2*pr][0] = r4[0]; kbl[2*pr][1] = r4[1];
                kbl[2*pr+1][0] = r4[2]; kbl[2*pr+1][1] = r4[3];
            }
#pragma unroll
            for (int nt = 0; nt < 8; nt++) {
                mma_bf16(accS[nt], ah, kbh[nt]);
                mma_bf16(accS[nt], ah, kbl[nt]);
                mma_bf16(accS[nt], al, kbh[nt]);
            }
        }

        // ---- scores + online-max softmax ----
        const int grow0 = qt*64 + w*16 + gid, grow1 = grow0 + 8;
        float rmax0 = -CUDART_INF_F, rmax1 = -CUDART_INF_F;
#pragma unroll
        for (int nt = 0; nt < 8; nt++) {
            const int lc = nt*8 + tig*2;
            const int gc0 = kt*64 + lc, gc1 = gc0 + 1;
            const float kn0 = kn[lc], kn1 = kn[lc + 1];
            float sv[4] = {accS[nt][0], accS[nt][1], accS[nt][2], accS[nt][3]};
            float qq[4] = {qn0, qn0, qn1, qn1};
            float kk[4] = {kn0, kn1, kn0, kn1};
            bool  ok[4] = {gc0 <= grow0, gc1 <= grow0, gc0 <= grow1, gc1 <= grow1};
#pragma unroll
            for (int e = 0; e < 4; e++) {
                float a    = qq[e] + kk[e];
                float diff = fmaxf(fmaf(-2.f, sv[e], a), 0.f) + 1e-8f;
                float prod = diff * fmaf(c, a, 1.f);
                float sc   = -beta * (prod * rsqrtf(prod));
                accS[nt][e] = ok[e] ? sc : -CUDART_INF_F;
            }
            rmax0 = fmaxf(rmax0, fmaxf(accS[nt][0], accS[nt][1]));
            rmax1 = fmaxf(rmax1, fmaxf(accS[nt][2], accS[nt][3]));
        }
        rmax0 = fmaxf(rmax0, __shfl_xor_sync(0xffffffffu, rmax0, 1));
        rmax0 = fmaxf(rmax0, __shfl_xor_sync(0xffffffffu, rmax0, 2));
        rmax1 = fmaxf(rmax1, __shfl_xor_sync(0xffffffffu, rmax1, 1));
        rmax1 = fmaxf(rmax1, __shfl_xor_sync(0xffffffffu, rmax1, 2));

        const float mn0 = fmaxf(m0, rmax0), mn1 = fmaxf(m1, rmax1);
        const float sc0 = __expf(m0 - mn0), sc1 = __expf(m1 - mn1);
        m0 = mn0; m1 = mn1;
        float rs0 = 0.f, rs1 = 0.f;
#pragma unroll
        for (int nt = 0; nt < 8; nt++) {
            accO[nt][0] *= sc0; accO[nt][1] *= sc0;
            accO[nt][2] *= sc1; accO[nt][3] *= sc1;
            float w0 = __expf(accS[nt][0] - mn0);
            float w1 = __expf(accS[nt][1] - mn0);
            float w2 = __expf(accS[nt][2] - mn1);
            float w3 = __expf(accS[nt][3] - mn1);
            accS[nt][0] = w0; accS[nt][1] = w1; accS[nt][2] = w2; accS[nt][3] = w3;
            rs0 += w0 + w1; rs1 += w2 + w3;
        }
        rs0 += __shfl_xor_sync(0xffffffffu, rs0, 1);
        rs0 += __shfl_xor_sync(0xffffffffu, rs0, 2);
        rs1 += __shfl_xor_sync(0xffffffffu, rs1, 1);
        rs1 += __shfl_xor_sync(0xffffffffu, rs1, 2);
        l0 = l0*sc0 + rs0; l1 = l1*sc1 + rs1;

        // ---- O += P V, P in fp16 (single), V split fp16 (hi + lo) ----
        const int vrow = ((lane >> 3) & 1) * 8 + (lane & 7);
        const int vcol = ((lane >> 4) & 1) * 8;
#pragma unroll
        for (int ks = 0; ks < 4; ks++) {
            uint32_t ph[4];
            ph[0] = packh2(accS[2*ks][0],   accS[2*ks][1]);
            ph[1] = packh2(accS[2*ks][2],   accS[2*ks][3]);
            ph[2] = packh2(accS[2*ks+1][0], accS[2*ks+1][1]);
            ph[3] = packh2(accS[2*ks+1][2], accS[2*ks+1][3]);
            uint32_t vbh[8][2], vbl[8][2];
#pragma unroll
            for (int pr = 0; pr < 4; pr++) {
                uint32_t r4[4];
                ldm_x4_trans(r4, smem_u32(&Vh[(ks*16 + vrow)*KSTR + pr*16 + vcol]));
                vbh[2*pr][0] = r4[0]; vbh[2*pr][1] = r4[1];
                vbh[2*pr+1][0] = r4[2]; vbh[2*pr+1][1] = r4[3];
                ldm_x4_trans(r4, smem_u32(&Vl[(ks*16 + vrow)*KSTR + pr*16 + vcol]));
                vbl[2*pr][0] = r4[0]; vbl[2*pr][1] = r4[1];
                vbl[2*pr+1][0] = r4[2]; vbl[2*pr+1][1] = r4[3];
            }
#pragma unroll
            for (int nt = 0; nt < 8; nt++) {
                mma_f16(accO[nt], ph, vbh[nt]);
                mma_f16(accO[nt], ph, vbl[nt]);
            }
        }
    }

    // ---- normalize + write O as split bf16, layout [b][n][h*64+d] ----
    const float inv0 = 1.f / l0, inv1 = 1.f / l1;
    const int row0 = qt*64 + w*16 + gid;
    const size_t base0 = ((size_t)b*SEQ + row0)*DM + h*DH;
    const size_t base1 = base0 + (size_t)8*DM;
#pragma unroll
    for (int nt = 0; nt < 8; nt++) {
        const int d = nt*8 + tig*2;
        uint32_t hh, ll;
        split2(accO[nt][0]*inv0, accO[nt][1]*inv0, hh, ll);
        *(uint32_t*)(g_Oh + base0 + d) = hh;
        *(uint32_t*)(g_Ol + base0 + d) = ll;
        split2(accO[nt][2]*inv1, accO[nt][3]*inv1, hh, ll);
        *(uint32_t*)(g_Oh + base1 + d) = hh;
        *(uint32_t*)(g_Ol + base1 + d) = ll;
    }
}

extern "C" void kernel_launch(void* const* d_in, const int* in_sizes, int n_in,
                              void* d_out, int out_size) {
    const float* x    = (const float*)d_in[0];
    const float* Wq   = (const float*)d_in[1];
    const float* Wk   = (const float*)d_in[2];
    const float* Wv   = (const float*)d_in[3];
    const float* Wo   = (const float*)d_in[4];
    const float* logc = (const float*)d_in[5];
    const float* logb = (const float*)d_in[6];
    if (in_sizes[0] != NB * SEQ * DM) {
        const float* xf = nullptr; const float* ws[4] = {}; const float* sc[2] = {};
        int nw = 0, ns = 0;
        for (int i = 0; i < n_in; i++) {
            if (in_sizes[i] == NB * SEQ * DM)          xf = (const float*)d_in[i];
            else if (in_sizes[i] == DM * DM && nw < 4) ws[nw++] = (const float*)d_in[i];
            else if (in_sizes[i] == 1 && ns < 2)       sc[ns++] = (const float*)d_in[i];
        }
        if (xf && nw == 4 && ns == 2) {
            x = xf; Wq = ws[0]; Wk = ws[1]; Wv = ws[2]; Wo = ws[3];
            logc = sc[0]; logb = sc[1];
        }
    }
    float* out = (float*)d_out;

    const int attn_smem = (6*64*KSTR)*2 + 64*4;   // 55552 B
    cudaFuncSetAttribute(attn_mma_kernel, cudaFuncAttributeMaxDynamicSharedMemorySize, attn_smem);

    cvt_x_kernel<<<(MROWS*DM/4 + 255)/256, 256>>>(x, MROWS*DM);
    dim3 wgrid(DM*DM/4/256, 4);
    cvt_w_kernel<<<wgrid, 256>>>(Wq, Wk, Wv, Wo);

    dim3 pgrid(DM / 128, MROWS / 128, 3);
    mma_gemm_kernel<0><<<pgrid, 256>>>(nullptr);

    dim3 agrid(SEQ / 64, NH, NB);
    attn_mma_kernel<<<agrid, 128, attn_smem>>>(logc, logb);

    dim3 ogrid(DM / 128, MROWS / 128, 1);
    mma_gemm_kernel<1><<<ogrid, 256>>>(out);
}

// round 10
// speedup vs baseline: 2.9921x; 1.0333x over previous
#include <cuda_runtime.h>
#include <cuda_bf16.h>
#include <cuda_fp16.h>
#include <math_constants.h>
#include <cstdint>

#define SEQ 2048
#define DM  512
#define NB  2
#define NH  8
#define DH  64
#define MROWS (NB*SEQ)   // 4096

// split activations, head-split layout [b][h][n][dh]
__device__ __align__(16) __nv_bfloat16 g_Qh[NB*NH*SEQ*DH], g_Ql[NB*NH*SEQ*DH];
__device__ __align__(16) __nv_bfloat16 g_Kh[NB*NH*SEQ*DH], g_Kl[NB*NH*SEQ*DH];
__device__ __align__(16) __half       g_Vh[NB*NH*SEQ*DH], g_Vl[NB*NH*SEQ*DH];
__device__ __align__(16) float        g_qn[NB*NH*SEQ], g_kn[NB*NH*SEQ];
// GEMM operands
__device__ __align__(16) __nv_bfloat16 g_xh[MROWS*DM], g_xl[MROWS*DM];
__device__ __align__(16) __nv_bfloat16 g_Wh[4*DM*DM],  g_Wl[4*DM*DM];
__device__ __align__(16) __nv_bfloat16 g_Oh[MROWS*DM], g_Ol[MROWS*DM];

// ---------------- helpers ----------------
__device__ __forceinline__ uint32_t smem_u32(const void* p) {
    uint32_t a;
    asm("{ .reg .u64 t; cvta.to.shared.u64 t, %1; cvt.u32.u64 %0, t; }" : "=r"(a) : "l"(p));
    return a;
}
#define CPA16(dst, src) asm volatile("cp.async.cg.shared.global [%0], [%1], 16;" :: "r"(dst), "l"(src) : "memory")
#define CP_COMMIT()     asm volatile("cp.async.commit_group;" ::: "memory")
#define CP_WAIT1()      asm volatile("cp.async.wait_group 1;" ::: "memory")

__device__ __forceinline__ void ldm_x4(uint32_t* r, uint32_t addr) {
    asm volatile("ldmatrix.sync.aligned.m8n8.x4.shared.b16 {%0,%1,%2,%3}, [%4];"
                 : "=r"(r[0]), "=r"(r[1]), "=r"(r[2]), "=r"(r[3]) : "r"(addr));
}
__device__ __forceinline__ void ldm_x4_trans(uint32_t* r, uint32_t addr) {
    asm volatile("ldmatrix.sync.aligned.m8n8.x4.trans.shared.b16 {%0,%1,%2,%3}, [%4];"
                 : "=r"(r[0]), "=r"(r[1]), "=r"(r[2]), "=r"(r[3]) : "r"(addr));
}
__device__ __forceinline__ void mma_bf16(float* d, const uint32_t* a, const uint32_t* b) {
    asm volatile("mma.sync.aligned.m16n8k16.row.col.f32.bf16.bf16.f32 "
                 "{%0,%1,%2,%3}, {%4,%5,%6,%7}, {%8,%9}, {%0,%1,%2,%3};"
                 : "+f"(d[0]), "+f"(d[1]), "+f"(d[2]), "+f"(d[3])
                 : "r"(a[0]), "r"(a[1]), "r"(a[2]), "r"(a[3]), "r"(b[0]), "r"(b[1]));
}
__device__ __forceinline__ void mma_f16(float* d, const uint32_t* a, const uint32_t* b) {
    asm volatile("mma.sync.aligned.m16n8k16.row.col.f32.f16.f16.f32 "
                 "{%0,%1,%2,%3}, {%4,%5,%6,%7}, {%8,%9}, {%0,%1,%2,%3};"
                 : "+f"(d[0]), "+f"(d[1]), "+f"(d[2]), "+f"(d[3])
                 : "r"(a[0]), "r"(a[1]), "r"(a[2]), "r"(a[3]), "r"(b[0]), "r"(b[1]));
}
__device__ __forceinline__ void split2(float a, float b, uint32_t& h, uint32_t& l) {
    __nv_bfloat16 ha = __float2bfloat16(a), hb = __float2bfloat16(b);
    __nv_bfloat16 la = __float2bfloat16(a - __bfloat162float(ha));
    __nv_bfloat16 lb = __float2bfloat16(b - __bfloat162float(hb));
    __nv_bfloat162 H; H.x = ha; H.y = hb;
    __nv_bfloat162 L; L.x = la; L.y = lb;
    h = *(uint32_t*)&H; l = *(uint32_t*)&L;
}
__device__ __forceinline__ void split2h(float a, float b, uint32_t& h, uint32_t& l) {
    __half ha = __float2half_rn(a), hb = __float2half_rn(b);
    __half la = __float2half_rn(a - __half2float(ha));
    __half lb = __float2half_rn(b - __half2float(hb));
    __half2 H; H.x = ha; H.y = hb;
    __half2 L; L.x = la; L.y = lb;
    h = *(uint32_t*)&H; l = *(uint32_t*)&L;
}
__device__ __forceinline__ uint32_t packh2(float a, float b) {
    __half2 h = __floats2half2_rn(a, b);
    return *(uint32_t*)&h;
}

// ---------------- conversions ----------------
__global__ void __launch_bounds__(256) cvt_x_kernel(const float* __restrict__ src, int n) {
    int i = (blockIdx.x * 256 + threadIdx.x) * 4;
    if (i >= n) return;
    float4 v = *(const float4*)(src + i);
    float vv[4] = {v.x, v.y, v.z, v.w};
#pragma unroll
    for (int k = 0; k < 4; k++) {
        __nv_bfloat16 h = __float2bfloat16(vv[k]);
        g_xh[i + k] = h;
        g_xl[i + k] = __float2bfloat16(vv[k] - __bfloat162float(h));
    }
}
__global__ void __launch_bounds__(256) cvt_w_kernel(const float* __restrict__ w0,
                                                    const float* __restrict__ w1,
                                                    const float* __restrict__ w2,
                                                    const float* __restrict__ w3) {
    const int z = blockIdx.y;
    const float* src = (z == 0) ? w0 : (z == 1) ? w1 : (z == 2) ? w2 : w3;
    int i = (blockIdx.x * 256 + threadIdx.x) * 4;
    __nv_bfloat16* dh = g_Wh + (size_t)z * DM * DM;
    __nv_bfloat16* dl = g_Wl + (size_t)z * DM * DM;
    float4 v = *(const float4*)(src + i);
    float vv[4] = {v.x, v.y, v.z, v.w};
#pragma unroll
    for (int k = 0; k < 4; k++) {
        __nv_bfloat16 h = __float2bfloat16(vv[k]);
        dh[i + k] = h;
        dl[i + k] = __float2bfloat16(vv[k] - __bfloat162float(h));
    }
}

// ---------------- split-bf16 GEMM via mma.sync, cp.async double-buffered ----------------
#define ASTR 40
#define GEMM_BUF_B   (128*ASTR*2)          // 10240 B per buffer
#define GEMM_STAGE_B (4*GEMM_BUF_B)        // 40960 B per stage
#define GEMM_SMEM    (2*GEMM_STAGE_B)      // 81920 B

template<int MODE>
__global__ void __launch_bounds__(256) mma_gemm_kernel(float* __restrict__ outp) {
    extern __shared__ __align__(16) char gsm[];
    const int t = threadIdx.x, lane = t & 31, w = t >> 5;
    const int wm = w & 3, wn = w >> 2;
    const int m0 = blockIdx.y * 128, j0 = blockIdx.x * 128;
    const int wsel = (MODE == 0) ? (int)blockIdx.z : 3;

    const __nv_bfloat16* Ahp = (MODE == 0) ? g_xh : g_Oh;
    const __nv_bfloat16* Alp = (MODE == 0) ? g_xl : g_Ol;
    const __nv_bfloat16* Whp = g_Wh + (size_t)wsel * DM * DM;
    const __nv_bfloat16* Wlp = g_Wl + (size_t)wsel * DM * DM;

    const uint32_t smb = smem_u32(gsm);

    float acc[2][8][4];
#pragma unroll
    for (int mt = 0; mt < 2; mt++)
#pragma unroll
        for (int nt = 0; nt < 8; nt++)
#pragma unroll
            for (int e = 0; e < 4; e++) acc[mt][nt][e] = 0.f;

    const int arow = wm*32 + (lane & 15);
    const int boff = ((lane >> 4) & 1) * 8;
    const int brow = wn*64 + (lane & 7) + ((lane >> 4) & 1) * 8;
    const int bcol = ((lane >> 3) & 1) * 8;

    // prologue: slab 0 -> stage 0
#pragma unroll
    for (int p = 0; p < 2; p++) {
        int id = t + 256 * p;
        int r = id >> 2, cc = id & 3;
        uint32_t off = (uint32_t)(r * ASTR * 2 + cc * 16);
        const size_t ga = (size_t)(m0 + r) * DM + cc*8;
        const size_t gb = (size_t)(j0 + r) * DM + cc*8;
        CPA16(smb + off,                Ahp + ga);
        CPA16(smb + GEMM_BUF_B + off,   Alp + ga);
        CPA16(smb + 2*GEMM_BUF_B + off, Whp + gb);
        CPA16(smb + 3*GEMM_BUF_B + off, Wlp + gb);
    }
    CP_COMMIT();

    for (int s = 0; s < DM/32; s++) {
        const int st = s & 1;
        __syncthreads();
        if (s + 1 < DM/32) {
            const uint32_t base = smb + (st ^ 1) * GEMM_STAGE_B;
#pragma unroll
            for (int p = 0; p < 2; p++) {
                int id = t + 256 * p;
                int r = id >> 2, cc = id & 3;
                uint32_t off = (uint32_t)(r * ASTR * 2 + cc * 16);
                const size_t ga = (size_t)(m0 + r) * DM + (s+1)*32 + cc*8;
                const size_t gb = (size_t)(j0 + r) * DM + (s+1)*32 + cc*8;
                CPA16(base + off,                Ahp + ga);
                CPA16(base + GEMM_BUF_B + off,   Alp + ga);
                CPA16(base + 2*GEMM_BUF_B + off, Whp + gb);
                CPA16(base + 3*GEMM_BUF_B + off, Wlp + gb);
            }
        }
        CP_COMMIT();
        CP_WAIT1();
        __syncthreads();

        const __nv_bfloat16* sAh = (const __nv_bfloat16*)(gsm + st * GEMM_STAGE_B);
        const __nv_bfloat16* sAl = sAh + 128*ASTR;
        const __nv_bfloat16* sBh = sAl + 128*ASTR;
        const __nv_bfloat16* sBl = sBh + 128*ASTR;

#pragma unroll
        for (int ks = 0; ks < 2; ks++) {
            uint32_t ah[2][4], al[2][4];
#pragma unroll
            for (int mt = 0; mt < 2; mt++) {
                ldm_x4(ah[mt], smem_u32(&sAh[(arow + mt*16)*ASTR + ks*16 + boff]));
                ldm_x4(al[mt], smem_u32(&sAl[(arow + mt*16)*ASTR + ks*16 + boff]));
            }
            uint32_t bh[8][2], bl[8][2];
#pragma unroll
            for (int pr = 0; pr < 4; pr++) {
                uint32_t r4[4];
                ldm_x4(r4, smem_u32(&sBh[(brow + pr*16)*ASTR + ks*16 + bcol]));
                bh[2*pr][0] = r4[0]; bh[2*pr][1] = r4[1];
                bh[2*pr+1][0] = r4[2]; bh[2*pr+1][1] = r4[3];
                ldm_x4(r4, smem_u32(&sBl[(brow + pr*16)*ASTR + ks*16 + bcol]));
                bl[2*pr][0] = r4[0]; bl[2*pr][1] = r4[1];
                bl[2*pr+1][0] = r4[2]; bl[2*pr+1][1] = r4[3];
            }
#pragma unroll
            for (int mt = 0; mt < 2; mt++)
#pragma unroll
                for (int nt = 0; nt < 8; nt++) {
                    mma_bf16(acc[mt][nt], ah[mt], bh[nt]);
                    mma_bf16(acc[mt][nt], ah[mt], bl[nt]);
                    mma_bf16(acc[mt][nt], al[mt], bh[nt]);
                }
        }
    }

    const int gid = lane >> 2, tig = lane & 3;
#pragma unroll
    for (int mt = 0; mt < 2; mt++) {
#pragma unroll
        for (int nt = 0; nt < 8; nt++) {
            const int mrow = m0 + wm*32 + mt*16 + gid;
            const int jcol = j0 + wn*64 + nt*8 + tig*2;
            if (MODE == 1) {
                *(float2*)(outp + (size_t)mrow * DM + jcol)     = make_float2(acc[mt][nt][0], acc[mt][nt][1]);
                *(float2*)(outp + (size_t)(mrow+8) * DM + jcol) = make_float2(acc[mt][nt][2], acc[mt][nt][3]);
            } else {
                const int hh = jcol >> 6, d = jcol & (DH-1);
                const int b0r = mrow >> 11, n0r = mrow & (SEQ-1);
                const size_t base = ((size_t)(b0r*NH + hh)*SEQ + n0r)*DH + d;
                uint32_t ph_, pl_;
                if (blockIdx.z == 2) {
                    split2h(acc[mt][nt][0], acc[mt][nt][1], ph_, pl_);
                    *(uint32_t*)(g_Vh + base) = ph_;
                    *(uint32_t*)(g_Vl + base) = pl_;
                    split2h(acc[mt][nt][2], acc[mt][nt][3], ph_, pl_);
                    *(uint32_t*)(g_Vh + base + 8*DH) = ph_;
                    *(uint32_t*)(g_Vl + base + 8*DH) = pl_;
                } else {
                    __nv_bfloat16* dsh = (blockIdx.z == 0) ? g_Qh : g_Kh;
                    __nv_bfloat16* dsl = (blockIdx.z == 0) ? g_Ql : g_Kl;
                    split2(acc[mt][nt][0], acc[mt][nt][1], ph_, pl_);
                    *(uint32_t*)(dsh + base) = ph_;
                    *(uint32_t*)(dsl + base) = pl_;
                    split2(acc[mt][nt][2], acc[mt][nt][3], ph_, pl_);
                    *(uint32_t*)(dsh + base + 8*DH) = ph_;
                    *(uint32_t*)(dsl + base + 8*DH) = pl_;
                }
            }
        }
    }

    if (MODE == 0 && blockIdx.z < 2) {
        float* np = (blockIdx.z == 0) ? g_qn : g_kn;
        const int hh = (j0 + wn*64) >> 6;
#pragma unroll
        for (int mt = 0; mt < 2; mt++) {
            float s0 = 0.f, s1 = 0.f;
#pragma unroll
            for (int nt = 0; nt < 8; nt++) {
                s0 = fmaf(acc[mt][nt][0], acc[mt][nt][0], fmaf(acc[mt][nt][1], acc[mt][nt][1], s0));
                s1 = fmaf(acc[mt][nt][2], acc[mt][nt][2], fmaf(acc[mt][nt][3], acc[mt][nt][3], s1));
            }
            s0 += __shfl_xor_sync(0xffffffffu, s0, 1);
            s0 += __shfl_xor_sync(0xffffffffu, s0, 2);
            s1 += __shfl_xor_sync(0xffffffffu, s1, 1);
            s1 += __shfl_xor_sync(0xffffffffu, s1, 2);
            if (tig == 0) {
                const int mrow = m0 + wm*32 + mt*16 + gid;
                const int b0r = mrow >> 11, n0r = mrow & (SEQ-1);
                np[(size_t)(b0r*NH + hh)*SEQ + n0r]     = s0;
                np[(size_t)(b0r*NH + hh)*SEQ + n0r + 8] = s1;
            }
        }
    }
}

// ---------------- mma.sync hyperbolic flash attention, cp.async double-buffered ----------------
#define KSTR 72
#define TILE_B (64*KSTR*2)                 // 9216 B per buffer
#define KV_STAGE_B (4*TILE_B)              // 36864 B
#define ATTN_Q_B (2*TILE_B)                // 18432
#define ATTN_KN0 (ATTN_Q_B + 2*KV_STAGE_B) // 92160
#define ATTN_SMEM (ATTN_KN0 + 2*256)       // 92672

__global__ void __launch_bounds__(128) attn_mma_kernel(const float* __restrict__ p_logc,
                                                       const float* __restrict__ p_logb) {
    extern __shared__ __align__(16) char smraw[];
    __nv_bfloat16* Qh = (__nv_bfloat16*)smraw;
    __nv_bfloat16* Ql = (__nv_bfloat16*)(smraw + TILE_B);
    const uint32_t smb = smem_u32(smraw);

    const int t = threadIdx.x, lane = t & 31, w = t >> 5;
    const int qt = (int)(gridDim.x - 1 - blockIdx.x);
    const int h = blockIdx.y, b = blockIdx.z;
    const int bh = b*NH + h;

    const float c    = log1pf(__expf(*p_logc));
    const float beta = log1pf(__expf(*p_logb)) + 0.5f;

    const int gid = lane >> 2, tig = lane & 3;

    const size_t qoff = ((size_t)bh*SEQ + qt*64) * DH;
#pragma unroll
    for (int p = 0; p < 4; p++) {
        int id = t + 128*p;
        int r = id >> 3, cc = id & 7;
        *(uint4*)&Qh[r*KSTR + cc*8] = *(const uint4*)(g_Qh + qoff + r*64 + cc*8);
        *(uint4*)&Ql[r*KSTR + cc*8] = *(const uint4*)(g_Ql + qoff + r*64 + cc*8);
    }
    const float qn0 = g_qn[(size_t)bh*SEQ + qt*64 + w*16 + gid];
    const float qn1 = g_qn[(size_t)bh*SEQ + qt*64 + w*16 + gid + 8];

    const int arow  = w*16 + (lane & 15);
    const int acsel = ((lane >> 4) & 1) * 8;
    const int brow  = (lane & 7) + ((lane >> 4) & 1) * 8;
    const int bcol  = ((lane >> 3) & 1) * 8;

    float accO[8][4];
#pragma unroll
    for (int nt = 0; nt < 8; nt++)
#pragma unroll
        for (int e = 0; e < 4; e++) accO[nt][e] = 0.f;
    float m0 = -CUDART_INF_F, m1 = -CUDART_INF_F, l0 = 0.f, l1 = 0.f;

    // prologue: tile 0 -> stage 0
    {
        const size_t koff = (size_t)bh*SEQ*DH;
        const uint32_t base = smb + ATTN_Q_B;
#pragma unroll
        for (int p = 0; p < 4; p++) {
            int id = t + 128*p;
            int r = id >> 3, cc = id & 7;
            uint32_t off = (uint32_t)(r*KSTR*2 + cc*16);
            CPA16(base + off,            g_Kh + koff + r*64 + cc*8);
            CPA16(base + TILE_B + off,   g_Kl + koff + r*64 + cc*8);
            CPA16(base + 2*TILE_B + off, g_Vh + koff + r*64 + cc*8);
            CPA16(base + 3*TILE_B + off, g_Vl + koff + r*64 + cc*8);
        }
        if (t < 16) CPA16(smb + ATTN_KN0 + t*16, g_kn + (size_t)bh*SEQ + t*4);
        CP_COMMIT();
    }

    for (int kt = 0; kt <= qt; kt++) {
        const int st = kt & 1;
        __syncthreads();
        if (kt + 1 <= qt) {
            const size_t koff = ((size_t)bh*SEQ + (kt+1)*64) * DH;
            const uint32_t base = smb + ATTN_Q_B + (st ^ 1) * KV_STAGE_B;
#pragma unroll
            for (int p = 0; p < 4; p++) {
                int id = t + 128*p;
                int r = id >> 3, cc = id & 7;
                uint32_t off = (uint32_t)(r*KSTR*2 + cc*16);
                CPA16(base + off,            g_Kh + koff + r*64 + cc*8);
                CPA16(base + TILE_B + off,   g_Kl + koff + r*64 + cc*8);
                CPA16(base + 2*TILE_B + off, g_Vh + koff + r*64 + cc*8);
                CPA16(base + 3*TILE_B + off, g_Vl + koff + r*64 + cc*8);
            }
            if (t < 16) CPA16(smb + ATTN_KN0 + (st^1)*256 + t*16,
                              g_kn + (size_t)bh*SEQ + (kt+1)*64 + t*4);
        }
        CP_COMMIT();
        CP_WAIT1();
        __syncthreads();

        const __nv_bfloat16* Kh = (const __nv_bfloat16*)(smraw + ATTN_Q_B + st*KV_STAGE_B);
        const __nv_bfloat16* Kl = (const __nv_bfloat16*)((const char*)Kh + TILE_B);
        const __half*        Vh = (const __half*)((const char*)Kh + 2*TILE_B);
        const __half*        Vl = (const __half*)((const char*)Kh + 3*TILE_B);
        const float*         kn = (const float*)(smraw + ATTN_KN0 + st*256);

        float accS[8][4];
#pragma unroll
        for (int nt = 0; nt < 8; nt++)
#pragma unroll
            for (int e = 0; e < 4; e++) accS[nt][e] = 0.f;
#pragma unroll
        for (int ks = 0; ks < 4; ks++) {
            uint32_t ah[4], al[4];
            ldm_x4(ah, smem_u32(&Qh[arow*KSTR + ks*16 + acsel]));
            ldm_x4(al, smem_u32(&Ql[arow*KSTR + ks*16 + acsel]));
            uint32_t kbh[8][2], kbl[8][2];
#pragma unroll
            for (int pr = 0; pr < 4; pr++) {
                uint32_t r4[4];
                ldm_x4(r4, smem_u32(&Kh[(brow + pr*16)*KSTR + ks*16 + bcol]));
                kbh[2*pr][0] = r4[0]; kbh[2*pr][1] = r4[1];
                kbh[2*pr+1][0] = r4[2]; kbh[2*pr+1][1] = r4[3];
                ldm_x4(r4, smem_u32(&Kl[(brow + pr*16)*KSTR + ks*16 + bcol]));
                kbl[2*pr][0] = r4[0]; kbl[2*pr][1] = r4[1];
                kbl[2*pr+1][0] = r4[2]; kbl[2*pr+1][1] = r4[3];
            }
#pragma unroll
            for (int nt = 0; nt < 8; nt++) {
                mma_bf16(accS[nt], ah, kbh[nt]);
                mma_bf16(accS[nt], ah, kbl[nt]);
                mma_bf16(accS[nt], al, kbh[nt]);
            }
        }

        const int grow0 = qt*64 + w*16 + gid, grow1 = grow0 + 8;
        float rmax0 = -CUDART_INF_F, rmax1 = -CUDART_INF_F;
#pragma unroll
        for (int nt = 0; nt < 8; nt++) {
            const int lc = nt*8 + tig*2;
            const int gc0 = kt*64 + lc, gc1 = gc0 + 1;
            const float kn0 = kn[lc], kn1 = kn[lc + 1];
            float sv[4] = {accS[nt][0], accS[nt][1], accS[nt][2], accS[nt][3]};
            float qq[4] = {qn0, qn0, qn1, qn1};
            float kk[4] = {kn0, kn1, kn0, kn1};
            bool  ok[4] = {gc0 <= grow0, gc1 <= grow0, gc0 <= grow1, gc1 <= grow1};
#pragma unroll
            for (int e = 0; e < 4; e++) {
                float a    = qq[e] + kk[e];
                float diff = fmaxf(fmaf(-2.f, sv[e], a), 0.f) + 1e-8f;
                float prod = diff * fmaf(c, a, 1.f);
                float sc   = -beta * (prod * rsqrtf(prod));
                accS[nt][e] = ok[e] ? sc : -CUDART_INF_F;
            }
            rmax0 = fmaxf(rmax0, fmaxf(accS[nt][0], accS[nt][1]));
            rmax1 = fmaxf(rmax1, fmaxf(accS[nt][2], accS[nt][3]));
        }
        rmax0 = fmaxf(rmax0, __shfl_xor_sync(0xffffffffu, rmax0, 1));
        rmax0 = fmaxf(rmax0, __shfl_xor_sync(0xffffffffu, rmax0, 2));
        rmax1 = fmaxf(rmax1, __shfl_xor_sync(0xffffffffu, rmax1, 1));
        rmax1 = fmaxf(rmax1, __shfl_xor_sync(0xffffffffu, rmax1, 2));

        const float mn0 = fmaxf(m0, rmax0), mn1 = fmaxf(m1, rmax1);
        const float sc0 = __expf(m0 - mn0), sc1 = __expf(m1 - mn1);
        m0 = mn0; m1 = mn1;
        float rs0 = 0.f, rs1 = 0.f;
#pragma unroll
        for (int nt = 0; nt < 8; nt++) {
            accO[nt][0] *= sc0; accO[nt][1] *= sc0;
            accO[nt][2] *= sc1; accO[nt][3] *= sc1;
            float w0 = __expf(accS[nt][0] - mn0);
            float w1 = __expf(accS[nt][1] - mn0);
            float w2 = __expf(accS[nt][2] - mn1);
            float w3 = __expf(accS[nt][3] - mn1);
            accS[nt][0] = w0; accS[nt][1] = w1; accS[nt][2] = w2; accS[nt][3] = w3;
            rs0 += w0 + w1; rs1 += w2 + w3;
        }
        rs0 += __shfl_xor_sync(0xffffffffu, rs0, 1);
        rs0 += __shfl_xor_sync(0xffffffffu, rs0, 2);
        rs1 += __shfl_xor_sync(0xffffffffu, rs1, 1);
        rs1 += __shfl_xor_sync(0xffffffffu, rs1, 2);
        l0 = l0*sc0 + rs0; l1 = l1*sc1 + rs1;

        const int vrow = ((lane >> 3) & 1) * 8 + (lane & 7);
        const int vcol = ((lane >> 4) & 1) * 8;
#pragma unroll
        for (int ks = 0; ks < 4; ks++) {
            uint32_t ph[4];
            ph[0] = packh2(accS[2*ks][0],   accS[2*ks][1]);
            ph[1] = packh2(accS[2*ks][2],   accS[2*ks][3]);
            ph[2] = packh2(accS[2*ks+1][0], accS[2*ks+1][1]);
            ph[3] = packh2(accS[2*ks+1][2], accS[2*ks+1][3]);
            uint32_t vbh[8][2], vbl[8][2];
#pragma unroll
            for (int pr = 0; pr < 4; pr++) {
                uint32_t r4[4];
                ldm_x4_trans(r4, smem_u32(&Vh[(ks*16 + vrow)*KSTR + pr*16 + vcol]));
                vbh[2*pr][0] = r4[0]; vbh[2*pr][1] = r4[1];
                vbh[2*pr+1][0] = r4[2]; vbh[2*pr+1][1] = r4[3];
                ldm_x4_trans(r4, smem_u32(&Vl[(ks*16 + vrow)*KSTR + pr*16 + vcol]));
                vbl[2*pr][0] = r4[0]; vbl[2*pr][1] = r4[1];
                vbl[2*pr+1][0] = r4[2]; vbl[2*pr+1][1] = r4[3];
            }
#pragma unroll
            for (int nt = 0; nt < 8; nt++) {
                mma_f16(accO[nt], ph, vbh[nt]);
                mma_f16(accO[nt], ph, vbl[nt]);
            }
        }
    }

    const float inv0 = 1.f / l0, inv1 = 1.f / l1;
    const int row0 = qt*64 + w*16 + gid;
    const size_t base0 = ((size_t)b*SEQ + row0)*DM + h*DH;
    const size_t base1 = base0 + (size_t)8*DM;
#pragma unroll
    for (int nt = 0; nt < 8; nt++) {
        const int d = nt*8 + tig*2;
        uint32_t hh, ll;
        split2(accO[nt][0]*inv0, accO[nt][1]*inv0, hh, ll);
        *(uint32_t*)(g_Oh + base0 + d) = hh;
        *(uint32_t*)(g_Ol + base0 + d) = ll;
        split2(accO[nt][2]*inv1, accO[nt][3]*inv1, hh, ll);
        *(uint32_t*)(g_Oh + base1 + d) = hh;
        *(uint32_t*)(g_Ol + base1 + d) = ll;
    }
}

extern "C" void kernel_launch(void* const* d_in, const int* in_sizes, int n_in,
                              void* d_out, int out_size) {
    const float* x    = (const float*)d_in[0];
    const float* Wq   = (const float*)d_in[1];
    const float* Wk   = (const float*)d_in[2];
    const float* Wv   = (const float*)d_in[3];
    const float* Wo   = (const float*)d_in[4];
    const float* logc = (const float*)d_in[5];
    const float* logb = (const float*)d_in[6];
    if (in_sizes[0] != NB * SEQ * DM) {
        const float* xf = nullptr; const float* ws[4] = {}; const float* sc[2] = {};
        int nw = 0, ns = 0;
        for (int i = 0; i < n_in; i++) {
            if (in_sizes[i] == NB * SEQ * DM)          xf = (const float*)d_in[i];
            else if (in_sizes[i] == DM * DM && nw < 4) ws[nw++] = (const float*)d_in[i];
            else if (in_sizes[i] == 1 && ns < 2)       sc[ns++] = (const float*)d_in[i];
        }
        if (xf && nw == 4 && ns == 2) {
            x = xf; Wq = ws[0]; Wk = ws[1]; Wv = ws[2]; Wo = ws[3];
            logc = sc[0]; logb = sc[1];
        }
    }
    float* out = (float*)d_out;

    cudaFuncSetAttribute(attn_mma_kernel,    cudaFuncAttributeMaxDynamicSharedMemorySize, ATTN_SMEM);
    cudaFuncSetAttribute(mma_gemm_kernel<0>, cudaFuncAttributeMaxDynamicSharedMemorySize, GEMM_SMEM);
    cudaFuncSetAttribute(mma_gemm_kernel<1>, cudaFuncAttributeMaxDynamicSharedMemorySize, GEMM_SMEM);

    cvt_x_kernel<<<(MROWS*DM/4 + 255)/256, 256>>>(x, MROWS*DM);
    dim3 wgrid(DM*DM/4/256, 4);
    cvt_w_kernel<<<wgrid, 256>>>(Wq, Wk, Wv, Wo);

    dim3 pgrid(DM / 128, MROWS / 128, 3);
    mma_gemm_kernel<0><<<pgrid, 256, GEMM_SMEM>>>(nullptr);

    dim3 agrid(SEQ / 64, NH, NB);
    attn_mma_kernel<<<agrid, 128, ATTN_SMEM>>>(logc, logb);

    dim3 ogrid(DM / 128, MROWS / 128, 1);
    mma_gemm_kernel<1><<<ogrid, 256, GEMM_SMEM>>>(out);
}

// round 11
// speedup vs baseline: 3.3600x; 1.1229x over previous
#include <cuda_runtime.h>
#include <cuda_bf16.h>
#include <cuda_fp16.h>
#include <math_constants.h>
#include <cstdint>

#define SEQ 2048
#define DM  512
#define NB  2
#define NH  8
#define DH  64
#define MROWS (NB*SEQ)   // 4096

// split activations, head-split layout [b][h][n][dh]
__device__ __align__(16) __nv_bfloat16 g_Qh[NB*NH*SEQ*DH], g_Ql[NB*NH*SEQ*DH];
__device__ __align__(16) __nv_bfloat16 g_Kh[NB*NH*SEQ*DH], g_Kl[NB*NH*SEQ*DH];
__device__ __align__(16) __half       g_Vh[NB*NH*SEQ*DH], g_Vl[NB*NH*SEQ*DH];
__device__ __align__(16) float        g_qn[NB*NH*SEQ], g_kn[NB*NH*SEQ];
// GEMM operands
__device__ __align__(16) __nv_bfloat16 g_xh[MROWS*DM], g_xl[MROWS*DM];
__device__ __align__(16) __nv_bfloat16 g_Wh[4*DM*DM],  g_Wl[4*DM*DM];
__device__ __align__(16) __nv_bfloat16 g_Oh[MROWS*DM], g_Ol[MROWS*DM];

// ---------------- helpers ----------------
__device__ __forceinline__ uint32_t smem_u32(const void* p) {
    uint32_t a;
    asm("{ .reg .u64 t; cvta.to.shared.u64 t, %1; cvt.u32.u64 %0, t; }" : "=r"(a) : "l"(p));
    return a;
}
#define CPA16(dst, src) asm volatile("cp.async.cg.shared.global [%0], [%1], 16;" :: "r"(dst), "l"(src) : "memory")
#define CP_COMMIT()     asm volatile("cp.async.commit_group;" ::: "memory")
#define CP_WAIT1()      asm volatile("cp.async.wait_group 1;" ::: "memory")
#define CP_WAIT2()      asm volatile("cp.async.wait_group 2;" ::: "memory")

__device__ __forceinline__ void ldm_x4(uint32_t* r, uint32_t addr) {
    asm volatile("ldmatrix.sync.aligned.m8n8.x4.shared.b16 {%0,%1,%2,%3}, [%4];"
                 : "=r"(r[0]), "=r"(r[1]), "=r"(r[2]), "=r"(r[3]) : "r"(addr));
}
__device__ __forceinline__ void ldm_x4_trans(uint32_t* r, uint32_t addr) {
    asm volatile("ldmatrix.sync.aligned.m8n8.x4.trans.shared.b16 {%0,%1,%2,%3}, [%4];"
                 : "=r"(r[0]), "=r"(r[1]), "=r"(r[2]), "=r"(r[3]) : "r"(addr));
}
__device__ __forceinline__ void mma_bf16(float* d, const uint32_t* a, const uint32_t* b) {
    asm volatile("mma.sync.aligned.m16n8k16.row.col.f32.bf16.bf16.f32 "
                 "{%0,%1,%2,%3}, {%4,%5,%6,%7}, {%8,%9}, {%0,%1,%2,%3};"
                 : "+f"(d[0]), "+f"(d[1]), "+f"(d[2]), "+f"(d[3])
                 : "r"(a[0]), "r"(a[1]), "r"(a[2]), "r"(a[3]), "r"(b[0]), "r"(b[1]));
}
__device__ __forceinline__ void mma_f16(float* d, const uint32_t* a, const uint32_t* b) {
    asm volatile("mma.sync.aligned.m16n8k16.row.col.f32.f16.f16.f32 "
                 "{%0,%1,%2,%3}, {%4,%5,%6,%7}, {%8,%9}, {%0,%1,%2,%3};"
                 : "+f"(d[0]), "+f"(d[1]), "+f"(d[2]), "+f"(d[3])
                 : "r"(a[0]), "r"(a[1]), "r"(a[2]), "r"(a[3]), "r"(b[0]), "r"(b[1]));
}
__device__ __forceinline__ void split2(float a, float b, uint32_t& h, uint32_t& l) {
    __nv_bfloat16 ha = __float2bfloat16(a), hb = __float2bfloat16(b);
    __nv_bfloat16 la = __float2bfloat16(a - __bfloat162float(ha));
    __nv_bfloat16 lb = __float2bfloat16(b - __bfloat162float(hb));
    __nv_bfloat162 H; H.x = ha; H.y = hb;
    __nv_bfloat162 L; L.x = la; L.y = lb;
    h = *(uint32_t*)&H; l = *(uint32_t*)&L;
}
__device__ __forceinline__ void split2h(float a, float b, uint32_t& h, uint32_t& l) {
    __half ha = __float2half_rn(a), hb = __float2half_rn(b);
    __half la = __float2half_rn(a - __half2float(ha));
    __half lb = __float2half_rn(b - __half2float(hb));
    __half2 H; H.x = ha; H.y = hb;
    __half2 L; L.x = la; L.y = lb;
    h = *(uint32_t*)&H; l = *(uint32_t*)&L;
}
__device__ __forceinline__ uint32_t packh2(float a, float b) {
    __half2 h = __floats2half2_rn(a, b);
    return *(uint32_t*)&h;
}

// ---------------- conversions ----------------
__global__ void __launch_bounds__(256) cvt_x_kernel(const float* __restrict__ src, int n) {
    int i = (blockIdx.x * 256 + threadIdx.x) * 4;
    if (i >= n) return;
    float4 v = *(const float4*)(src + i);
    float vv[4] = {v.x, v.y, v.z, v.w};
#pragma unroll
    for (int k = 0; k < 4; k++) {
        __nv_bfloat16 h = __float2bfloat16(vv[k]);
        g_xh[i + k] = h;
        g_xl[i + k] = __float2bfloat16(vv[k] - __bfloat162float(h));
    }
}
__global__ void __launch_bounds__(256) cvt_w_kernel(const float* __restrict__ w0,
                                                    const float* __restrict__ w1,
                                                    const float* __restrict__ w2,
                                                    const float* __restrict__ w3) {
    const int z = blockIdx.y;
    const float* src = (z == 0) ? w0 : (z == 1) ? w1 : (z == 2) ? w2 : w3;
    int i = (blockIdx.x * 256 + threadIdx.x) * 4;
    __nv_bfloat16* dh = g_Wh + (size_t)z * DM * DM;
    __nv_bfloat16* dl = g_Wl + (size_t)z * DM * DM;
    float4 v = *(const float4*)(src + i);
    float vv[4] = {v.x, v.y, v.z, v.w};
#pragma unroll
    for (int k = 0; k < 4; k++) {
        __nv_bfloat16 h = __float2bfloat16(vv[k]);
        dh[i + k] = h;
        dl[i + k] = __float2bfloat16(vv[k] - __bfloat162float(h));
    }
}

// ---------------- split-bf16 GEMM via mma.sync, cp.async double-buffered ----------------
#define ASTR 40
#define GEMM_BUF_B   (128*ASTR*2)          // 10240 B per buffer
#define GEMM_STAGE_B (4*GEMM_BUF_B)        // 40960 B per stage
#define GEMM_SMEM    (2*GEMM_STAGE_B)      // 81920 B

template<int MODE>
__global__ void __launch_bounds__(256) mma_gemm_kernel(float* __restrict__ outp) {
    extern __shared__ __align__(16) char gsm[];
    const int t = threadIdx.x, lane = t & 31, w = t >> 5;
    const int wm = w & 3, wn = w >> 2;
    const int m0 = blockIdx.y * 128, j0 = blockIdx.x * 128;
    const int wsel = (MODE == 0) ? (int)blockIdx.z : 3;

    const __nv_bfloat16* Ahp = (MODE == 0) ? g_xh : g_Oh;
    const __nv_bfloat16* Alp = (MODE == 0) ? g_xl : g_Ol;
    const __nv_bfloat16* Whp = g_Wh + (size_t)wsel * DM * DM;
    const __nv_bfloat16* Wlp = g_Wl + (size_t)wsel * DM * DM;

    const uint32_t smb = smem_u32(gsm);

    float acc[2][8][4];
#pragma unroll
    for (int mt = 0; mt < 2; mt++)
#pragma unroll
        for (int nt = 0; nt < 8; nt++)
#pragma unroll
            for (int e = 0; e < 4; e++) acc[mt][nt][e] = 0.f;

    const int arow = wm*32 + (lane & 15);
    const int boff = ((lane >> 4) & 1) * 8;
    const int brow = wn*64 + (lane & 7) + ((lane >> 4) & 1) * 8;
    const int bcol = ((lane >> 3) & 1) * 8;

    // prologue: slab 0 -> stage 0
#pragma unroll
    for (int p = 0; p < 2; p++) {
        int id = t + 256 * p;
        int r = id >> 2, cc = id & 3;
        uint32_t off = (uint32_t)(r * ASTR * 2 + cc * 16);
        const size_t ga = (size_t)(m0 + r) * DM + cc*8;
        const size_t gb = (size_t)(j0 + r) * DM + cc*8;
        CPA16(smb + off,                Ahp + ga);
        CPA16(smb + GEMM_BUF_B + off,   Alp + ga);
        CPA16(smb + 2*GEMM_BUF_B + off, Whp + gb);
        CPA16(smb + 3*GEMM_BUF_B + off, Wlp + gb);
    }
    CP_COMMIT();

    for (int s = 0; s < DM/32; s++) {
        const int st = s & 1;
        __syncthreads();
        if (s + 1 < DM/32) {
            const uint32_t base = smb + (st ^ 1) * GEMM_STAGE_B;
#pragma unroll
            for (int p = 0; p < 2; p++) {
                int id = t + 256 * p;
                int r = id >> 2, cc = id & 3;
                uint32_t off = (uint32_t)(r * ASTR * 2 + cc * 16);
                const size_t ga = (size_t)(m0 + r) * DM + (s+1)*32 + cc*8;
                const size_t gb = (size_t)(j0 + r) * DM + (s+1)*32 + cc*8;
                CPA16(base + off,                Ahp + ga);
                CPA16(base + GEMM_BUF_B + off,   Alp + ga);
                CPA16(base + 2*GEMM_BUF_B + off, Whp + gb);
                CPA16(base + 3*GEMM_BUF_B + off, Wlp + gb);
            }
        }
        CP_COMMIT();
        CP_WAIT1();
        __syncthreads();

        const __nv_bfloat16* sAh = (const __nv_bfloat16*)(gsm + st * GEMM_STAGE_B);
        const __nv_bfloat16* sAl = sAh + 128*ASTR;
        const __nv_bfloat16* sBh = sAl + 128*ASTR;
        const __nv_bfloat16* sBl = sBh + 128*ASTR;

#pragma unroll
        for (int ks = 0; ks < 2; ks++) {
            uint32_t ah[2][4], al[2][4];
#pragma unroll
            for (int mt = 0; mt < 2; mt++) {
                ldm_x4(ah[mt], smem_u32(&sAh[(arow + mt*16)*ASTR + ks*16 + boff]));
                ldm_x4(al[mt], smem_u32(&sAl[(arow + mt*16)*ASTR + ks*16 + boff]));
            }
            uint32_t bh[8][2], bl[8][2];
#pragma unroll
            for (int pr = 0; pr < 4; pr++) {
                uint32_t r4[4];
                ldm_x4(r4, smem_u32(&sBh[(brow + pr*16)*ASTR + ks*16 + bcol]));
                bh[2*pr][0] = r4[0]; bh[2*pr][1] = r4[1];
                bh[2*pr+1][0] = r4[2]; bh[2*pr+1][1] = r4[3];
                ldm_x4(r4, smem_u32(&sBl[(brow + pr*16)*ASTR + ks*16 + bcol]));
                bl[2*pr][0] = r4[0]; bl[2*pr][1] = r4[1];
                bl[2*pr+1][0] = r4[2]; bl[2*pr+1][1] = r4[3];
            }
#pragma unroll
            for (int mt = 0; mt < 2; mt++)
#pragma unroll
                for (int nt = 0; nt < 8; nt++) {
                    mma_bf16(acc[mt][nt], ah[mt], bh[nt]);
                    mma_bf16(acc[mt][nt], ah[mt], bl[nt]);
                    mma_bf16(acc[mt][nt], al[mt], bh[nt]);
                }
        }
    }

    const int gid = lane >> 2, tig = lane & 3;
#pragma unroll
    for (int mt = 0; mt < 2; mt++) {
#pragma unroll
        for (int nt = 0; nt < 8; nt++) {
            const int mrow = m0 + wm*32 + mt*16 + gid;
            const int jcol = j0 + wn*64 + nt*8 + tig*2;
            if (MODE == 1) {
                *(float2*)(outp + (size_t)mrow * DM + jcol)     = make_float2(acc[mt][nt][0], acc[mt][nt][1]);
                *(float2*)(outp + (size_t)(mrow+8) * DM + jcol) = make_float2(acc[mt][nt][2], acc[mt][nt][3]);
            } else {
                const int hh = jcol >> 6, d = jcol & (DH-1);
                const int b0r = mrow >> 11, n0r = mrow & (SEQ-1);
                const size_t base = ((size_t)(b0r*NH + hh)*SEQ + n0r)*DH + d;
                uint32_t ph_, pl_;
                if (blockIdx.z == 2) {
                    split2h(acc[mt][nt][0], acc[mt][nt][1], ph_, pl_);
                    *(uint32_t*)(g_Vh + base) = ph_;
                    *(uint32_t*)(g_Vl + base) = pl_;
                    split2h(acc[mt][nt][2], acc[mt][nt][3], ph_, pl_);
                    *(uint32_t*)(g_Vh + base + 8*DH) = ph_;
                    *(uint32_t*)(g_Vl + base + 8*DH) = pl_;
                } else {
                    __nv_bfloat16* dsh = (blockIdx.z == 0) ? g_Qh : g_Kh;
                    __nv_bfloat16* dsl = (blockIdx.z == 0) ? g_Ql : g_Kl;
                    split2(acc[mt][nt][0], acc[mt][nt][1], ph_, pl_);
                    *(uint32_t*)(dsh + base) = ph_;
                    *(uint32_t*)(dsl + base) = pl_;
                    split2(acc[mt][nt][2], acc[mt][nt][3], ph_, pl_);
                    *(uint32_t*)(dsh + base + 8*DH) = ph_;
                    *(uint32_t*)(dsl + base + 8*DH) = pl_;
                }
            }
        }
    }

    if (MODE == 0 && blockIdx.z < 2) {
        float* np = (blockIdx.z == 0) ? g_qn : g_kn;
        const int hh = (j0 + wn*64) >> 6;
#pragma unroll
        for (int mt = 0; mt < 2; mt++) {
            float s0 = 0.f, s1 = 0.f;
#pragma unroll
            for (int nt = 0; nt < 8; nt++) {
                s0 = fmaf(acc[mt][nt][0], acc[mt][nt][0], fmaf(acc[mt][nt][1], acc[mt][nt][1], s0));
                s1 = fmaf(acc[mt][nt][2], acc[mt][nt][2], fmaf(acc[mt][nt][3], acc[mt][nt][3], s1));
            }
            s0 += __shfl_xor_sync(0xffffffffu, s0, 1);
            s0 += __shfl_xor_sync(0xffffffffu, s0, 2);
            s1 += __shfl_xor_sync(0xffffffffu, s1, 1);
            s1 += __shfl_xor_sync(0xffffffffu, s1, 2);
            if (tig == 0) {
                const int mrow = m0 + wm*32 + mt*16 + gid;
                const int b0r = mrow >> 11, n0r = mrow & (SEQ-1);
                np[(size_t)(b0r*NH + hh)*SEQ + n0r]     = s0;
                np[(size_t)(b0r*NH + hh)*SEQ + n0r + 8] = s1;
            }
        }
    }
}

// ---------------- mma.sync hyperbolic flash attention ----------------
// Smem budget tuned for 3 CTAs/SM: Q + double-buffered K + single V + kn = 73984 B.
#define KSTR 72
#define TILE_B (64*KSTR*2)                 // 9216 B per buffer
#define AK_ST  (2*TILE_B)                  // 18432 B per K stage (Kh,Kl)
#define AK0    (2*TILE_B)                  // K stages start after Qh,Ql
#define AV0    (AK0 + 2*AK_ST)             // 55296
#define AKN    (AV0 + 2*TILE_B)            // 73728
#define ATTN_SMEM (AKN + 256)              // 73984

__global__ void __launch_bounds__(128, 3) attn_mma_kernel(const float* __restrict__ p_logc,
                                                          const float* __restrict__ p_logb) {
    extern __shared__ __align__(16) char smraw[];
    __nv_bfloat16* Qh = (__nv_bfloat16*)smraw;
    __nv_bfloat16* Ql = (__nv_bfloat16*)(smraw + TILE_B);
    const uint32_t smb = smem_u32(smraw);

    const int t = threadIdx.x, lane = t & 31, w = t >> 5;
    const int qt = (int)(gridDim.x - 1 - blockIdx.x);
    const int h = blockIdx.y, b = blockIdx.z;
    const int bh = b*NH + h;

    const float c    = log1pf(__expf(*p_logc));
    const float beta = log1pf(__expf(*p_logb)) + 0.5f;

    const int gid = lane >> 2, tig = lane & 3;

    const size_t qoff = ((size_t)bh*SEQ + qt*64) * DH;
#pragma unroll
    for (int p = 0; p < 4; p++) {
        int id = t + 128*p;
        int r = id >> 3, cc = id & 7;
        *(uint4*)&Qh[r*KSTR + cc*8] = *(const uint4*)(g_Qh + qoff + r*64 + cc*8);
        *(uint4*)&Ql[r*KSTR + cc*8] = *(const uint4*)(g_Ql + qoff + r*64 + cc*8);
    }
    const float qn0 = g_qn[(size_t)bh*SEQ + qt*64 + w*16 + gid];
    const float qn1 = g_qn[(size_t)bh*SEQ + qt*64 + w*16 + gid + 8];

    const int arow  = w*16 + (lane & 15);
    const int acsel = ((lane >> 4) & 1) * 8;
    const int brow  = (lane & 7) + ((lane >> 4) & 1) * 8;
    const int bcol  = ((lane >> 3) & 1) * 8;

    float accO[8][4];
#pragma unroll
    for (int nt = 0; nt < 8; nt++)
#pragma unroll
        for (int e = 0; e < 4; e++) accO[nt][e] = 0.f;
    float m0 = -CUDART_INF_F, m1 = -CUDART_INF_F, l0 = 0.f, l1 = 0.f;

    // prologue: K(0) -> stage 0  (group chain "B")
    {
        const size_t koff = (size_t)bh*SEQ*DH;
        const uint32_t base = smb + AK0;
#pragma unroll
        for (int p = 0; p < 4; p++) {
            int id = t + 128*p;
            int r = id >> 3, cc = id & 7;
            uint32_t off = (uint32_t)(r*KSTR*2 + cc*16);
            CPA16(base + off,          g_Kh + koff + r*64 + cc*8);
            CPA16(base + TILE_B + off, g_Kl + koff + r*64 + cc*8);
        }
        CP_COMMIT();
    }

    for (int kt = 0; kt <= qt; kt++) {
        const int st = kt & 1;
        __syncthreads();   // V/kn buffers reusable; K stage st^1 write-safe

        // group A: V(kt) + kn(kt)
        {
            const size_t koff = ((size_t)bh*SEQ + kt*64) * DH;
#pragma unroll
            for (int p = 0; p < 4; p++) {
                int id = t + 128*p;
                int r = id >> 3, cc = id & 7;
                uint32_t off = (uint32_t)(r*KSTR*2 + cc*16);
                CPA16(smb + AV0 + off,          g_Vh + koff + r*64 + cc*8);
                CPA16(smb + AV0 + TILE_B + off, g_Vl + koff + r*64 + cc*8);
            }
            if (t < 16) CPA16(smb + AKN + t*16, g_kn + (size_t)bh*SEQ + kt*64 + t*4);
            CP_COMMIT();
        }
        // group B: K(kt+1) -> stage st^1
        if (kt + 1 <= qt) {
            const size_t koff = ((size_t)bh*SEQ + (kt+1)*64) * DH;
            const uint32_t base = smb + AK0 + (st ^ 1) * AK_ST;
#pragma unroll
            for (int p = 0; p < 4; p++) {
                int id = t + 128*p;
                int r = id >> 3, cc = id & 7;
                uint32_t off = (uint32_t)(r*KSTR*2 + cc*16);
                CPA16(base + off,          g_Kh + koff + r*64 + cc*8);
                CPA16(base + TILE_B + off, g_Kl + koff + r*64 + cc*8);
            }
        }
        CP_COMMIT();
        CP_WAIT2();        // K(kt) group drained (A_kt, B_kt may still fly)
        __syncthreads();

        const __nv_bfloat16* Kh = (const __nv_bfloat16*)(smraw + AK0 + st*AK_ST);
        const __nv_bfloat16* Kl = (const __nv_bfloat16*)((const char*)Kh + TILE_B);

        // ---- S = Q K^T ----
        float accS[8][4];
#pragma unroll
        for (int nt = 0; nt < 8; nt++)
#pragma unroll
            for (int e = 0; e < 4; e++) accS[nt][e] = 0.f;
#pragma unroll
        for (int ks = 0; ks < 4; ks++) {
            uint32_t ah[4], al[4];
            ldm_x4(ah, smem_u32(&Qh[arow*KSTR + ks*16 + acsel]));
            ldm_x4(al, smem_u32(&Ql[arow*KSTR + ks*16 + acsel]));
            uint32_t kbh[8][2], kbl[8][2];
#pragma unroll
            for (int pr = 0; pr < 4; pr++) {
                uint32_t r4[4];
                ldm_x4(r4, smem_u32(&Kh[(brow + pr*16)*KSTR + ks*16 + bcol]));
                kbh[2*pr][0] = r4[0]; kbh[2*pr][1] = r4[1];
                kbh[2*pr+1][0] = r4[2]; kbh[2*pr+1][1] = r4[3];
                ldm_x4(r4, smem_u32(&Kl[(brow + pr*16)*KSTR + ks*16 + bcol]));
                kbl[2*pr][0] = r4[0]; kbl[2*pr][1] = r4[1];
                kbl[2*pr+1][0] = r4[2]; kbl[2*pr+1][1] = r4[3];
            }
#pragma unroll
            for (int nt = 0; nt < 8; nt++) {
                mma_bf16(accS[nt], ah, kbh[nt]);
                mma_bf16(accS[nt], ah, kbl[nt]);
                mma_bf16(accS[nt], al, kbh[nt]);
            }
        }

        CP_WAIT1();        // A_kt (V + kn) drained; K(kt+1) still flying
        __syncthreads();

        const __half* Vh = (const __half*)(smraw + AV0);
        const __half* Vl = (const __half*)(smraw + AV0 + TILE_B);
        const float*  kn = (const float*)(smraw + AKN);

        // ---- scores + online-max softmax ----
        const int grow0 = qt*64 + w*16 + gid, grow1 = grow0 + 8;
        float rmax0 = -CUDART_INF_F, rmax1 = -CUDART_INF_F;
#pragma unroll
        for (int nt = 0; nt < 8; nt++) {
            const int lc = nt*8 + tig*2;
            const int gc0 = kt*64 + lc, gc1 = gc0 + 1;
            const float kn0 = kn[lc], kn1 = kn[lc + 1];
            float sv[4] = {accS[nt][0], accS[nt][1], accS[nt][2], accS[nt][3]};
            float qq[4] = {qn0, qn0, qn1, qn1};
            float kk[4] = {kn0, kn1, kn0, kn1};
            bool  ok[4] = {gc0 <= grow0, gc1 <= grow0, gc0 <= grow1, gc1 <= grow1};
#pragma unroll
            for (int e = 0; e < 4; e++) {
                float a    = qq[e] + kk[e];
                float diff = fmaxf(fmaf(-2.f, sv[e], a), 0.f) + 1e-8f;
                float prod = diff * fmaf(c, a, 1.f);
                float sc   = -beta * (prod * rsqrtf(prod));
                accS[nt][e] = ok[e] ? sc : -CUDART_INF_F;
            }
            rmax0 = fmaxf(rmax0, fmaxf(accS[nt][0], accS[nt][1]));
            rmax1 = fmaxf(rmax1, fmaxf(accS[nt][2], accS[nt][3]));
        }
        rmax0 = fmaxf(rmax0, __shfl_xor_sync(0xffffffffu, rmax0, 1));
        rmax0 = fmaxf(rmax0, __shfl_xor_sync(0xffffffffu, rmax0, 2));
        rmax1 = fmaxf(rmax1, __shfl_xor_sync(0xffffffffu, rmax1, 1));
        rmax1 = fmaxf(rmax1, __shfl_xor_sync(0xffffffffu, rmax1, 2));

        const float mn0 = fmaxf(m0, rmax0), mn1 = fmaxf(m1, rmax1);
        const float sc0 = __expf(m0 - mn0), sc1 = __expf(m1 - mn1);
        m0 = mn0; m1 = mn1;
        float rs0 = 0.f, rs1 = 0.f;
#pragma unroll
        for (int nt = 0; nt < 8; nt++) {
            accO[nt][0] *= sc0; accO[nt][1] *= sc0;
            accO[nt][2] *= sc1; accO[nt][3] *= sc1;
            float w0 = __expf(accS[nt][0] - mn0);
            float w1 = __expf(accS[nt][1] - mn0);
            float w2 = __expf(accS[nt][2] - mn1);
            float w3 = __expf(accS[nt][3] - mn1);
            accS[nt][0] = w0; accS[nt][1] = w1; accS[nt][2] = w2; accS[nt][3] = w3;
            rs0 += w0 + w1; rs1 += w2 + w3;
        }
        rs0 += __shfl_xor_sync(0xffffffffu, rs0, 1);
        rs0 += __shfl_xor_sync(0xffffffffu, rs0, 2);
        rs1 += __shfl_xor_sync(0xffffffffu, rs1, 1);
        rs1 += __shfl_xor_sync(0xffffffffu, rs1, 2);
        l0 = l0*sc0 + rs0; l1 = l1*sc1 + rs1;

        // ---- O += P V ----
        const int vrow = ((lane >> 3) & 1) * 8 + (lane & 7);
        const int vcol = ((lane >> 4) & 1) * 8;
#pragma unroll
        for (int ks = 0; ks < 4; ks++) {
            uint32_t ph[4];
            ph[0] = packh2(accS[2*ks][0],   accS[2*ks][1]);
            ph[1] = packh2(accS[2*ks][2],   accS[2*ks][3]);
            ph[2] = packh2(accS[2*ks+1][0], accS[2*ks+1][1]);
            ph[3] = packh2(accS[2*ks+1][2], accS[2*ks+1][3]);
            uint32_t vbh[8][2], vbl[8][2];
#pragma unroll
            for (int pr = 0; pr < 4; pr++) {
                uint32_t r4[4];
                ldm_x4_trans(r4, smem_u32(&Vh[(ks*16 + vrow)*KSTR + pr*16 + vcol]));
                vbh[2*pr][0] = r4[0]; vbh[2*pr][1] = r4[1];
                vbh[2*pr+1][0] = r4[2]; vbh[2*pr+1][1] = r4[3];
                ldm_x4_trans(r4, smem_u32(&Vl[(ks*16 + vrow)*KSTR + pr*16 + vcol]));
                vbl[2*pr][0] = r4[0]; vbl[2*pr][1] = r4[1];
                vbl[2*pr+1][0] = r4[2]; vbl[2*pr+1][1] = r4[3];
            }
#pragma unroll
            for (int nt = 0; nt < 8; nt++) {
                mma_f16(accO[nt], ph, vbh[nt]);
                mma_f16(accO[nt], ph, vbl[nt]);
            }
        }
    }

    const float inv0 = 1.f / l0, inv1 = 1.f / l1;
    const int row0 = qt*64 + w*16 + gid;
    const size_t base0 = ((size_t)b*SEQ + row0)*DM + h*DH;
    const size_t base1 = base0 + (size_t)8*DM;
#pragma unroll
    for (int nt = 0; nt < 8; nt++) {
        const int d = nt*8 + tig*2;
        uint32_t hh, ll;
        split2(accO[nt][0]*inv0, accO[nt][1]*inv0, hh, ll);
        *(uint32_t*)(g_Oh + base0 + d) = hh;
        *(uint32_t*)(g_Ol + base0 + d) = ll;
        split2(accO[nt][2]*inv1, accO[nt][3]*inv1, hh, ll);
        *(uint32_t*)(g_Oh + base1 + d) = hh;
        *(uint32_t*)(g_Ol + base1 + d) = ll;
    }
}

extern "C" void kernel_launch(void* const* d_in, const int* in_sizes, int n_in,
                              void* d_out, int out_size) {
    const float* x    = (const float*)d_in[0];
    const float* Wq   = (const float*)d_in[1];
    const float* Wk   = (const float*)d_in[2];
    const float* Wv   = (const float*)d_in[3];
    const float* Wo   = (const float*)d_in[4];
    const float* logc = (const float*)d_in[5];
    const float* logb = (const float*)d_in[6];
    if (in_sizes[0] != NB * SEQ * DM) {
        const float* xf = nullptr; const float* ws[4] = {}; const float* sc[2] = {};
        int nw = 0, ns = 0;
        for (int i = 0; i < n_in; i++) {
            if (in_sizes[i] == NB * SEQ * DM)          xf = (const float*)d_in[i];
            else if (in_sizes[i] == DM * DM && nw < 4) ws[nw++] = (const float*)d_in[i];
            else if (in_sizes[i] == 1 && ns < 2)       sc[ns++] = (const float*)d_in[i];
        }
        if (xf && nw == 4 && ns == 2) {
            x = xf; Wq = ws[0]; Wk = ws[1]; Wv = ws[2]; Wo = ws[3];
            logc = sc[0]; logb = sc[1];
        }
    }
    float* out = (float*)d_out;

    cudaFuncSetAttribute(attn_mma_kernel,    cudaFuncAttributeMaxDynamicSharedMemorySize, ATTN_SMEM);
    cudaFuncSetAttribute(mma_gemm_kernel<0>, cudaFuncAttributeMaxDynamicSharedMemorySize, GEMM_SMEM);
    cudaFuncSetAttribute(mma_gemm_kernel<1>, cudaFuncAttributeMaxDynamicSharedMemorySize, GEMM_SMEM);

    cvt_x_kernel<<<(MROWS*DM/4 + 255)/256, 256>>>(x, MROWS*DM);
    dim3 wgrid(DM*DM/4/256, 4);
    cvt_w_kernel<<<wgrid, 256>>>(Wq, Wk, Wv, Wo);

    dim3 pgrid(DM / 128, MROWS / 128, 3);
    mma_gemm_kernel<0><<<pgrid, 256, GEMM_SMEM>>>(nullptr);

    dim3 agrid(SEQ / 64, NH, NB);
    attn_mma_kernel<<<agrid, 128, ATTN_SMEM>>>(logc, logb);

    dim3 ogrid(DM / 128, MROWS / 128, 1);
    mma_gemm_kernel<1><<<ogrid, 256, GEMM_SMEM>>>(out);
}

// round 12
// speedup vs baseline: 3.3805x; 1.0061x over previous
#include <cuda_runtime.h>
#include <cuda_bf16.h>
#include <cuda_fp16.h>
#include <math_constants.h>
#include <cstdint>

#define SEQ 2048
#define DM  512
#define NB  2
#define NH  8
#define DH  64
#define MROWS (NB*SEQ)   // 4096

// split activations, head-split layout [b][h][n][dh]
__device__ __align__(16) __nv_bfloat16 g_Qh[NB*NH*SEQ*DH], g_Ql[NB*NH*SEQ*DH];
__device__ __align__(16) __nv_bfloat16 g_Kh[NB*NH*SEQ*DH], g_Kl[NB*NH*SEQ*DH];
__device__ __align__(16) __half       g_Vh[NB*NH*SEQ*DH], g_Vl[NB*NH*SEQ*DH];
__device__ __align__(16) float        g_qn[NB*NH*SEQ], g_kn[NB*NH*SEQ];
// GEMM operands
__device__ __align__(16) __nv_bfloat16 g_xh[MROWS*DM], g_xl[MROWS*DM];
__device__ __align__(16) __nv_bfloat16 g_Wh[4*DM*DM],  g_Wl[4*DM*DM];
__device__ __align__(16) __nv_bfloat16 g_Oh[MROWS*DM], g_Ol[MROWS*DM];
// split-KV partial scratch: 512 jobs x (64x64 accO fp32) + (64 x {m,l})
__device__ __align__(16) float g_pO[512*4096];
__device__ __align__(16) float g_pml[512*128];

// ---------------- helpers ----------------
__device__ __forceinline__ uint32_t smem_u32(const void* p) {
    uint32_t a;
    asm("{ .reg .u64 t; cvta.to.shared.u64 t, %1; cvt.u32.u64 %0, t; }" : "=r"(a) : "l"(p));
    return a;
}
#define CPA16(dst, src) asm volatile("cp.async.cg.shared.global [%0], [%1], 16;" :: "r"(dst), "l"(src) : "memory")
#define CP_COMMIT()     asm volatile("cp.async.commit_group;" ::: "memory")
#define CP_WAIT1()      asm volatile("cp.async.wait_group 1;" ::: "memory")
#define CP_WAIT2()      asm volatile("cp.async.wait_group 2;" ::: "memory")

__device__ __forceinline__ void ldm_x4(uint32_t* r, uint32_t addr) {
    asm volatile("ldmatrix.sync.aligned.m8n8.x4.shared.b16 {%0,%1,%2,%3}, [%4];"
                 : "=r"(r[0]), "=r"(r[1]), "=r"(r[2]), "=r"(r[3]) : "r"(addr));
}
__device__ __forceinline__ void ldm_x4_trans(uint32_t* r, uint32_t addr) {
    asm volatile("ldmatrix.sync.aligned.m8n8.x4.trans.shared.b16 {%0,%1,%2,%3}, [%4];"
                 : "=r"(r[0]), "=r"(r[1]), "=r"(r[2]), "=r"(r[3]) : "r"(addr));
}
__device__ __forceinline__ void mma_bf16(float* d, const uint32_t* a, const uint32_t* b) {
    asm volatile("mma.sync.aligned.m16n8k16.row.col.f32.bf16.bf16.f32 "
                 "{%0,%1,%2,%3}, {%4,%5,%6,%7}, {%8,%9}, {%0,%1,%2,%3};"
                 : "+f"(d[0]), "+f"(d[1]), "+f"(d[2]), "+f"(d[3])
                 : "r"(a[0]), "r"(a[1]), "r"(a[2]), "r"(a[3]), "r"(b[0]), "r"(b[1]));
}
__device__ __forceinline__ void mma_f16(float* d, const uint32_t* a, const uint32_t* b) {
    asm volatile("mma.sync.aligned.m16n8k16.row.col.f32.f16.f16.f32 "
                 "{%0,%1,%2,%3}, {%4,%5,%6,%7}, {%8,%9}, {%0,%1,%2,%3};"
                 : "+f"(d[0]), "+f"(d[1]), "+f"(d[2]), "+f"(d[3])
                 : "r"(a[0]), "r"(a[1]), "r"(a[2]), "r"(a[3]), "r"(b[0]), "r"(b[1]));
}
__device__ __forceinline__ void split2(float a, float b, uint32_t& h, uint32_t& l) {
    __nv_bfloat16 ha = __float2bfloat16(a), hb = __float2bfloat16(b);
    __nv_bfloat16 la = __float2bfloat16(a - __bfloat162float(ha));
    __nv_bfloat16 lb = __float2bfloat16(b - __bfloat162float(hb));
    __nv_bfloat162 H; H.x = ha; H.y = hb;
    __nv_bfloat162 L; L.x = la; L.y = lb;
    h = *(uint32_t*)&H; l = *(uint32_t*)&L;
}
__device__ __forceinline__ void split2h(float a, float b, uint32_t& h, uint32_t& l) {
    __half ha = __float2half_rn(a), hb = __float2half_rn(b);
    __half la = __float2half_rn(a - __half2float(ha));
    __half lb = __float2half_rn(b - __half2float(hb));
    __half2 H; H.x = ha; H.y = hb;
    __half2 L; L.x = la; L.y = lb;
    h = *(uint32_t*)&H; l = *(uint32_t*)&L;
}
__device__ __forceinline__ uint32_t packh2(float a, float b) {
    __half2 h = __floats2half2_rn(a, b);
    return *(uint32_t*)&h;
}

// ---------------- conversions ----------------
__global__ void __launch_bounds__(256) cvt_x_kernel(const float* __restrict__ src, int n) {
    int i = (blockIdx.x * 256 + threadIdx.x) * 4;
    if (i >= n) return;
    float4 v = *(const float4*)(src + i);
    float vv[4] = {v.x, v.y, v.z, v.w};
#pragma unroll
    for (int k = 0; k < 4; k++) {
        __nv_bfloat16 h = __float2bfloat16(vv[k]);
        g_xh[i + k] = h;
        g_xl[i + k] = __float2bfloat16(vv[k] - __bfloat162float(h));
    }
}
__global__ void __launch_bounds__(256) cvt_w_kernel(const float* __restrict__ w0,
                                                    const float* __restrict__ w1,
                                                    const float* __restrict__ w2,
                                                    const float* __restrict__ w3) {
    const int z = blockIdx.y;
    const float* src = (z == 0) ? w0 : (z == 1) ? w1 : (z == 2) ? w2 : w3;
    int i = (blockIdx.x * 256 + threadIdx.x) * 4;
    __nv_bfloat16* dh = g_Wh + (size_t)z * DM * DM;
    __nv_bfloat16* dl = g_Wl + (size_t)z * DM * DM;
    float4 v = *(const float4*)(src + i);
    float vv[4] = {v.x, v.y, v.z, v.w};
#pragma unroll
    for (int k = 0; k < 4; k++) {
        __nv_bfloat16 h = __float2bfloat16(vv[k]);
        dh[i + k] = h;
        dl[i + k] = __float2bfloat16(vv[k] - __bfloat162float(h));
    }
}

// ---------------- split-bf16 GEMM via mma.sync, cp.async double-buffered ----------------
#define ASTR 40
#define GEMM_BUF_B   (128*ASTR*2)          // 10240 B per buffer
#define GEMM_STAGE_B (4*GEMM_BUF_B)        // 40960 B per stage
#define GEMM_SMEM    (2*GEMM_STAGE_B)      // 81920 B

template<int MODE>
__global__ void __launch_bounds__(256) mma_gemm_kernel(float* __restrict__ outp) {
    extern __shared__ __align__(16) char gsm[];
    const int t = threadIdx.x, lane = t & 31, w = t >> 5;
    const int wm = w & 3, wn = w >> 2;
    const int m0 = blockIdx.y * 128, j0 = blockIdx.x * 128;
    const int wsel = (MODE == 0) ? (int)blockIdx.z : 3;

    const __nv_bfloat16* Ahp = (MODE == 0) ? g_xh : g_Oh;
    const __nv_bfloat16* Alp = (MODE == 0) ? g_xl : g_Ol;
    const __nv_bfloat16* Whp = g_Wh + (size_t)wsel * DM * DM;
    const __nv_bfloat16* Wlp = g_Wl + (size_t)wsel * DM * DM;

    const uint32_t smb = smem_u32(gsm);

    float acc[2][8][4];
#pragma unroll
    for (int mt = 0; mt < 2; mt++)
#pragma unroll
        for (int nt = 0; nt < 8; nt++)
#pragma unroll
            for (int e = 0; e < 4; e++) acc[mt][nt][e] = 0.f;

    const int arow = wm*32 + (lane & 15);
    const int boff = ((lane >> 4) & 1) * 8;
    const int brow = wn*64 + (lane & 7) + ((lane >> 4) & 1) * 8;
    const int bcol = ((lane >> 3) & 1) * 8;

#pragma unroll
    for (int p = 0; p < 2; p++) {
        int id = t + 256 * p;
        int r = id >> 2, cc = id & 3;
        uint32_t off = (uint32_t)(r * ASTR * 2 + cc * 16);
        const size_t ga = (size_t)(m0 + r) * DM + cc*8;
        const size_t gb = (size_t)(j0 + r) * DM + cc*8;
        CPA16(smb + off,                Ahp + ga);
        CPA16(smb + GEMM_BUF_B + off,   Alp + ga);
        CPA16(smb + 2*GEMM_BUF_B + off, Whp + gb);
        CPA16(smb + 3*GEMM_BUF_B + off, Wlp + gb);
    }
    CP_COMMIT();

    for (int s = 0; s < DM/32; s++) {
        const int st = s & 1;
        __syncthreads();
        if (s + 1 < DM/32) {
            const uint32_t base = smb + (st ^ 1) * GEMM_STAGE_B;
#pragma unroll
            for (int p = 0; p < 2; p++) {
                int id = t + 256 * p;
                int r = id >> 2, cc = id & 3;
                uint32_t off = (uint32_t)(r * ASTR * 2 + cc * 16);
                const size_t ga = (size_t)(m0 + r) * DM + (s+1)*32 + cc*8;
                const size_t gb = (size_t)(j0 + r) * DM + (s+1)*32 + cc*8;
                CPA16(base + off,                Ahp + ga);
                CPA16(base + GEMM_BUF_B + off,   Alp + ga);
                CPA16(base + 2*GEMM_BUF_B + off, Whp + gb);
                CPA16(base + 3*GEMM_BUF_B + off, Wlp + gb);
            }
        }
        CP_COMMIT();
        CP_WAIT1();
        __syncthreads();

        const __nv_bfloat16* sAh = (const __nv_bfloat16*)(gsm + st * GEMM_STAGE_B);
        const __nv_bfloat16* sAl = sAh + 128*ASTR;
        const __nv_bfloat16* sBh = sAl + 128*ASTR;
        const __nv_bfloat16* sBl = sBh + 128*ASTR;

#pragma unroll
        for (int ks = 0; ks < 2; ks++) {
            uint32_t ah[2][4], al[2][4];
#pragma unroll
            for (int mt = 0; mt < 2; mt++) {
                ldm_x4(ah[mt], smem_u32(&sAh[(arow + mt*16)*ASTR + ks*16 + boff]));
                ldm_x4(al[mt], smem_u32(&sAl[(arow + mt*16)*ASTR + ks*16 + boff]));
            }
            uint32_t bh[8][2], bl[8][2];
#pragma unroll
            for (int pr = 0; pr < 4; pr++) {
                uint32_t r4[4];
                ldm_x4(r4, smem_u32(&sBh[(brow + pr*16)*ASTR + ks*16 + bcol]));
                bh[2*pr][0] = r4[0]; bh[2*pr][1] = r4[1];
                bh[2*pr+1][0] = r4[2]; bh[2*pr+1][1] = r4[3];
                ldm_x4(r4, smem_u32(&sBl[(brow + pr*16)*ASTR + ks*16 + bcol]));
                bl[2*pr][0] = r4[0]; bl[2*pr][1] = r4[1];
                bl[2*pr+1][0] = r4[2]; bl[2*pr+1][1] = r4[3];
            }
#pragma unroll
            for (int mt = 0; mt < 2; mt++)
#pragma unroll
                for (int nt = 0; nt < 8; nt++) {
                    mma_bf16(acc[mt][nt], ah[mt], bh[nt]);
                    mma_bf16(acc[mt][nt], ah[mt], bl[nt]);
                    mma_bf16(acc[mt][nt], al[mt], bh[nt]);
                }
        }
    }

    const int gid = lane >> 2, tig = lane & 3;
#pragma unroll
    for (int mt = 0; mt < 2; mt++) {
#pragma unroll
        for (int nt = 0; nt < 8; nt++) {
            const int mrow = m0 + wm*32 + mt*16 + gid;
            const int jcol = j0 + wn*64 + nt*8 + tig*2;
            if (MODE == 1) {
                *(float2*)(outp + (size_t)mrow * DM + jcol)     = make_float2(acc[mt][nt][0], acc[mt][nt][1]);
                *(float2*)(outp + (size_t)(mrow+8) * DM + jcol) = make_float2(acc[mt][nt][2], acc[mt][nt][3]);
            } else {
                const int hh = jcol >> 6, d = jcol & (DH-1);
                const int b0r = mrow >> 11, n0r = mrow & (SEQ-1);
                const size_t base = ((size_t)(b0r*NH + hh)*SEQ + n0r)*DH + d;
                uint32_t ph_, pl_;
                if (blockIdx.z == 2) {
                    split2h(acc[mt][nt][0], acc[mt][nt][1], ph_, pl_);
                    *(uint32_t*)(g_Vh + base) = ph_;
                    *(uint32_t*)(g_Vl + base) = pl_;
                    split2h(acc[mt][nt][2], acc[mt][nt][3], ph_, pl_);
                    *(uint32_t*)(g_Vh + base + 8*DH) = ph_;
                    *(uint32_t*)(g_Vl + base + 8*DH) = pl_;
                } else {
                    __nv_bfloat16* dsh = (blockIdx.z == 0) ? g_Qh : g_Kh;
                    __nv_bfloat16* dsl = (blockIdx.z == 0) ? g_Ql : g_Kl;
                    split2(acc[mt][nt][0], acc[mt][nt][1], ph_, pl_);
                    *(uint32_t*)(dsh + base) = ph_;
                    *(uint32_t*)(dsl + base) = pl_;
                    split2(acc[mt][nt][2], acc[mt][nt][3], ph_, pl_);
                    *(uint32_t*)(dsh + base + 8*DH) = ph_;
                    *(uint32_t*)(dsl + base + 8*DH) = pl_;
                }
            }
        }
    }

    if (MODE == 0 && blockIdx.z < 2) {
        float* np = (blockIdx.z == 0) ? g_qn : g_kn;
        const int hh = (j0 + wn*64) >> 6;
#pragma unroll
        for (int mt = 0; mt < 2; mt++) {
            float s0 = 0.f, s1 = 0.f;
#pragma unroll
            for (int nt = 0; nt < 8; nt++) {
                s0 = fmaf(acc[mt][nt][0], acc[mt][nt][0], fmaf(acc[mt][nt][1], acc[mt][nt][1], s0));
                s1 = fmaf(acc[mt][nt][2], acc[mt][nt][2], fmaf(acc[mt][nt][3], acc[mt][nt][3], s1));
            }
            s0 += __shfl_xor_sync(0xffffffffu, s0, 1);
            s0 += __shfl_xor_sync(0xffffffffu, s0, 2);
            s1 += __shfl_xor_sync(0xffffffffu, s1, 1);
            s1 += __shfl_xor_sync(0xffffffffu, s1, 2);
            if (tig == 0) {
                const int mrow = m0 + wm*32 + mt*16 + gid;
                const int b0r = mrow >> 11, n0r = mrow & (SEQ-1);
                np[(size_t)(b0r*NH + hh)*SEQ + n0r]     = s0;
                np[(size_t)(b0r*NH + hh)*SEQ + n0r + 8] = s1;
            }
        }
    }
}

// ---------------- mma.sync hyperbolic flash attention, split-KV balanced ----------------
// Jobs (grid.x = 48 per (h,b)):
//   jx in [0,32):  qt = 31 - (jx>>1), split = jx&1  -> half the kt range, fp32 partials
//   jx in [32,48): qt = 47 - jx                      -> full range, final split-bf16 O
#define KSTR 72
#define TILE_B (64*KSTR*2)                 // 9216 B per buffer
#define AK_ST  (2*TILE_B)                  // 18432 B per K stage (Kh,Kl)
#define AK0    (2*TILE_B)
#define AV0    (AK0 + 2*AK_ST)             // 55296
#define AKN    (AV0 + 2*TILE_B)            // 73728
#define ATTN_SMEM (AKN + 256)              // 73984

__global__ void __launch_bounds__(128, 3) attn_mma_kernel(const float* __restrict__ p_logc,
                                                          const float* __restrict__ p_logb) {
    extern __shared__ __align__(16) char smraw[];
    __nv_bfloat16* Qh = (__nv_bfloat16*)smraw;
    __nv_bfloat16* Ql = (__nv_bfloat16*)(smraw + TILE_B);
    const uint32_t smb = smem_u32(smraw);

    const int t = threadIdx.x, lane = t & 31, w = t >> 5;
    const int jx = (int)blockIdx.x;
    const int h = blockIdx.y, b = blockIdx.z;
    const int bh = b*NH + h;

    int qt, k0, k1, sp;
    bool partial;
    if (jx < 32) {
        qt = 31 - (jx >> 1);
        sp = jx & 1;
        const int mid = (qt + 1) >> 1;
        k0 = sp ? mid : 0;
        k1 = sp ? (qt + 1) : mid;
        partial = true;
    } else {
        qt = 47 - jx; k0 = 0; k1 = qt + 1; sp = 0; partial = false;
    }

    const float c    = log1pf(__expf(*p_logc));
    const float beta = log1pf(__expf(*p_logb)) + 0.5f;

    const int gid = lane >> 2, tig = lane & 3;

    const size_t qoff = ((size_t)bh*SEQ + qt*64) * DH;
#pragma unroll
    for (int p = 0; p < 4; p++) {
        int id = t + 128*p;
        int r = id >> 3, cc = id & 7;
        *(uint4*)&Qh[r*KSTR + cc*8] = *(const uint4*)(g_Qh + qoff + r*64 + cc*8);
        *(uint4*)&Ql[r*KSTR + cc*8] = *(const uint4*)(g_Ql + qoff + r*64 + cc*8);
    }
    const float qn0 = g_qn[(size_t)bh*SEQ + qt*64 + w*16 + gid];
    const float qn1 = g_qn[(size_t)bh*SEQ + qt*64 + w*16 + gid + 8];

    const int arow  = w*16 + (lane & 15);
    const int acsel = ((lane >> 4) & 1) * 8;
    const int brow  = (lane & 7) + ((lane >> 4) & 1) * 8;
    const int bcol  = ((lane >> 3) & 1) * 8;

    float accO[8][4];
#pragma unroll
    for (int nt = 0; nt < 8; nt++)
#pragma unroll
        for (int e = 0; e < 4; e++) accO[nt][e] = 0.f;
    float m0 = -CUDART_INF_F, m1 = -CUDART_INF_F, l0 = 0.f, l1 = 0.f;

    // prologue: K(k0) -> stage 0
    {
        const size_t koff = ((size_t)bh*SEQ + k0*64) * DH;
        const uint32_t base = smb + AK0;
#pragma unroll
        for (int p = 0; p < 4; p++) {
            int id = t + 128*p;
            int r = id >> 3, cc = id & 7;
            uint32_t off = (uint32_t)(r*KSTR*2 + cc*16);
            CPA16(base + off,          g_Kh + koff + r*64 + cc*8);
            CPA16(base + TILE_B + off, g_Kl + koff + r*64 + cc*8);
        }
        CP_COMMIT();
    }

    for (int kt = k0; kt < k1; kt++) {
        const int st = (kt - k0) & 1;
        __syncthreads();

        // group A: V(kt) + kn(kt)
        {
            const size_t koff = ((size_t)bh*SEQ + kt*64) * DH;
#pragma unroll
            for (int p = 0; p < 4; p++) {
                int id = t + 128*p;
                int r = id >> 3, cc = id & 7;
                uint32_t off = (uint32_t)(r*KSTR*2 + cc*16);
                CPA16(smb + AV0 + off,          g_Vh + koff + r*64 + cc*8);
                CPA16(smb + AV0 + TILE_B + off, g_Vl + koff + r*64 + cc*8);
            }
            if (t < 16) CPA16(smb + AKN + t*16, g_kn + (size_t)bh*SEQ + kt*64 + t*4);
            CP_COMMIT();
        }
        // group B: K(kt+1) -> stage st^1
        if (kt + 1 < k1) {
            const size_t koff = ((size_t)bh*SEQ + (kt+1)*64) * DH;
            const uint32_t base = smb + AK0 + (st ^ 1) * AK_ST;
#pragma unroll
            for (int p = 0; p < 4; p++) {
                int id = t + 128*p;
                int r = id >> 3, cc = id & 7;
                uint32_t off = (uint32_t)(r*KSTR*2 + cc*16);
                CPA16(base + off,          g_Kh + koff + r*64 + cc*8);
                CPA16(base + TILE_B + off, g_Kl + koff + r*64 + cc*8);
            }
        }
        CP_COMMIT();
        CP_WAIT2();
        __syncthreads();

        const __nv_bfloat16* Kh = (const __nv_bfloat16*)(smraw + AK0 + st*AK_ST);
        const __nv_bfloat16* Kl = (const __nv_bfloat16*)((const char*)Kh + TILE_B);

        // ---- S = Q K^T ----
        float accS[8][4];
#pragma unroll
        for (int nt = 0; nt < 8; nt++)
#pragma unroll
            for (int e = 0; e < 4; e++) accS[nt][e] = 0.f;
#pragma unroll
        for (int ks = 0; ks < 4; ks++) {
            uint32_t ah[4], al[4];
            ldm_x4(ah, smem_u32(&Qh[arow*KSTR + ks*16 + acsel]));
            ldm_x4(al, smem_u32(&Ql[arow*KSTR + ks*16 + acsel]));
            uint32_t kbh[8][2], kbl[8][2];
#pragma unroll
            for (int pr = 0; pr < 4; pr++) {
                uint32_t r4[4];
                ldm_x4(r4, smem_u32(&Kh[(brow + pr*16)*KSTR + ks*16 + bcol]));
                kbh[2*pr][0] = r4[0]; kbh[2*pr][1] = r4[1];
                kbh[2*pr+1][0] = r4[2]; kbh[2*pr+1][1] = r4[3];
                ldm_x4(r4, smem_u32(&Kl[(brow + pr*16)*KSTR + ks*16 + bcol]));
                kbl[2*pr][0] = r4[0]; kbl[2*pr][1] = r4[1];
                kbl[2*pr+1][0] = r4[2]; kbl[2*pr+1][1] = r4[3];
            }
#pragma unroll
            for (int nt = 0; nt < 8; nt++) {
                mma_bf16(accS[nt], ah, kbh[nt]);
                mma_bf16(accS[nt], ah, kbl[nt]);
                mma_bf16(accS[nt], al, kbh[nt]);
            }
        }

        CP_WAIT1();
        __syncthreads();

        const __half* Vh = (const __half*)(smraw + AV0);
        const __half* Vl = (const __half*)(smraw + AV0 + TILE_B);
        const float*  kn = (const float*)(smraw + AKN);

        // ---- scores + online-max softmax ----
        const int grow0 = qt*64 + w*16 + gid, grow1 = grow0 + 8;
        float rmax0 = -CUDART_INF_F, rmax1 = -CUDART_INF_F;
#pragma unroll
        for (int nt = 0; nt < 8; nt++) {
            const int lc = nt*8 + tig*2;
            const int gc0 = kt*64 + lc, gc1 = gc0 + 1;
            const float kn0 = kn[lc], kn1 = kn[lc + 1];
            float sv[4] = {accS[nt][0], accS[nt][1], accS[nt][2], accS[nt][3]};
            float qq[4] = {qn0, qn0, qn1, qn1};
            float kk[4] = {kn0, kn1, kn0, kn1};
            bool  ok[4] = {gc0 <= grow0, gc1 <= grow0, gc0 <= grow1, gc1 <= grow1};
#pragma unroll
            for (int e = 0; e < 4; e++) {
                float a    = qq[e] + kk[e];
                float diff = fmaxf(fmaf(-2.f, sv[e], a), 0.f) + 1e-8f;
                float prod = diff * fmaf(c, a, 1.f);
                float sc   = -beta * (prod * rsqrtf(prod));
                accS[nt][e] = ok[e] ? sc : -CUDART_INF_F;
            }
            rmax0 = fmaxf(rmax0, fmaxf(accS[nt][0], accS[nt][1]));
            rmax1 = fmaxf(rmax1, fmaxf(accS[nt][2], accS[nt][3]));
        }
        rmax0 = fmaxf(rmax0, __shfl_xor_sync(0xffffffffu, rmax0, 1));
        rmax0 = fmaxf(rmax0, __shfl_xor_sync(0xffffffffu, rmax0, 2));
        rmax1 = fmaxf(rmax1, __shfl_xor_sync(0xffffffffu, rmax1, 1));
        rmax1 = fmaxf(rmax1, __shfl_xor_sync(0xffffffffu, rmax1, 2));

        const float mn0 = fmaxf(m0, rmax0), mn1 = fmaxf(m1, rmax1);
        const float sc0 = __expf(m0 - mn0), sc1 = __expf(m1 - mn1);
        m0 = mn0; m1 = mn1;
        float rs0 = 0.f, rs1 = 0.f;
#pragma unroll
        for (int nt = 0; nt < 8; nt++) {
            accO[nt][0] *= sc0; accO[nt][1] *= sc0;
            accO[nt][2] *= sc1; accO[nt][3] *= sc1;
            float w0 = __expf(accS[nt][0] - mn0);
            float w1 = __expf(accS[nt][1] - mn0);
            float w2 = __expf(accS[nt][2] - mn1);
            float w3 = __expf(accS[nt][3] - mn1);
            accS[nt][0] = w0; accS[nt][1] = w1; accS[nt][2] = w2; accS[nt][3] = w3;
            rs0 += w0 + w1; rs1 += w2 + w3;
        }
        rs0 += __shfl_xor_sync(0xffffffffu, rs0, 1);
        rs0 += __shfl_xor_sync(0xffffffffu, rs0, 2);
        rs1 += __shfl_xor_sync(0xffffffffu, rs1, 1);
        rs1 += __shfl_xor_sync(0xffffffffu, rs1, 2);
        l0 = l0*sc0 + rs0; l1 = l1*sc1 + rs1;

        // ---- O += P V ----
        const int vrow = ((lane >> 3) & 1) * 8 + (lane & 7);
        const int vcol = ((lane >> 4) & 1) * 8;
#pragma unroll
        for (int ks = 0; ks < 4; ks++) {
            uint32_t ph[4];
            ph[0] = packh2(accS[2*ks][0],   accS[2*ks][1]);
            ph[1] = packh2(accS[2*ks][2],   accS[2*ks][3]);
            ph[2] = packh2(accS[2*ks+1][0], accS[2*ks+1][1]);
            ph[3] = packh2(accS[2*ks+1][2], accS[2*ks+1][3]);
            uint32_t vbh[8][2], vbl[8][2];
#pragma unroll
            for (int pr = 0; pr < 4; pr++) {
                uint32_t r4[4];
                ldm_x4_trans(r4, smem_u32(&Vh[(ks*16 + vrow)*KSTR + pr*16 + vcol]));
                vbh[2*pr][0] = r4[0]; vbh[2*pr][1] = r4[1];
                vbh[2*pr+1][0] = r4[2]; vbh[2*pr+1][1] = r4[3];
                ldm_x4_trans(r4, smem_u32(&Vl[(ks*16 + vrow)*KSTR + pr*16 + vcol]));
                vbl[2*pr][0] = r4[0]; vbl[2*pr][1] = r4[1];
                vbl[2*pr+1][0] = r4[2]; vbl[2*pr+1][1] = r4[3];
            }
#pragma unroll
            for (int nt = 0; nt < 8; nt++) {
                mma_f16(accO[nt], ph, vbh[nt]);
                mma_f16(accO[nt], ph, vbl[nt]);
            }
        }
    }

    const int rloc = w*16 + gid;
    if (partial) {
        // ---- write unnormalized fp32 partials + (m, l) ----
        const int job = ((bh)*16 + (qt - 16))*2 + sp;
        float* pO = g_pO + (size_t)job*4096;
#pragma unroll
        for (int nt = 0; nt < 8; nt++) {
            const int col = nt*8 + tig*2;
            *(float2*)(pO + rloc*64 + col)     = make_float2(accO[nt][0], accO[nt][1]);
            *(float2*)(pO + (rloc+8)*64 + col) = make_float2(accO[nt][2], accO[nt][3]);
        }
        if (tig == 0) {
            float* pml = g_pml + (size_t)job*128;
            pml[rloc*2]       = m0;  pml[rloc*2 + 1]       = l0;
            pml[(rloc+8)*2]   = m1;  pml[(rloc+8)*2 + 1]   = l1;
        }
    } else {
        const float inv0 = 1.f / l0, inv1 = 1.f / l1;
        const int row0 = qt*64 + rloc;
        const size_t base0 = ((size_t)b*SEQ + row0)*DM + h*DH;
        const size_t base1 = base0 + (size_t)8*DM;
#pragma unroll
        for (int nt = 0; nt < 8; nt++) {
            const int d = nt*8 + tig*2;
            uint32_t hh, ll;
            split2(accO[nt][0]*inv0, accO[nt][1]*inv0, hh, ll);
            *(uint32_t*)(g_Oh + base0 + d) = hh;
            *(uint32_t*)(g_Ol + base0 + d) = ll;
            split2(accO[nt][2]*inv1, accO[nt][3]*inv1, hh, ll);
            *(uint32_t*)(g_Oh + base1 + d) = hh;
            *(uint32_t*)(g_Ol + base1 + d) = ll;
        }
    }
}

// ---------------- split-KV reduction: combine 2 partials -> split-bf16 O ----------------
__global__ void __launch_bounds__(256) attn_reduce_kernel() {
    const int qi = blockIdx.x, h = blockIdx.y, b = blockIdx.z;
    const int t = threadIdx.x;
    const int r = t >> 2, c0 = (t & 3) * 16;
    const int jb = ((b*NH + h)*16 + qi)*2;

    const float* pml0 = g_pml + (size_t)jb*128;
    const float* pml1 = g_pml + (size_t)(jb+1)*128;
    const float m0 = pml0[r*2], l0 = pml0[r*2 + 1];
    const float m1 = pml1[r*2], l1 = pml1[r*2 + 1];
    const float M  = fmaxf(m0, m1);
    const float w0 = __expf(m0 - M), w1 = __expf(m1 - M);
    const float inv = 1.f / (l0*w0 + l1*w1);

    const float* A0 = g_pO + (size_t)jb*4096     + r*64 + c0;
    const float* A1 = g_pO + (size_t)(jb+1)*4096 + r*64 + c0;
    const int row = (16 + qi)*64 + r;
    __nv_bfloat16* oh = g_Oh + ((size_t)b*SEQ + row)*DM + h*DH + c0;
    __nv_bfloat16* ol = g_Ol + ((size_t)b*SEQ + row)*DM + h*DH + c0;

#pragma unroll
    for (int cc = 0; cc < 16; cc += 4) {
        float4 a0 = *(const float4*)(A0 + cc);
        float4 a1 = *(const float4*)(A1 + cc);
        float o0 = (a0.x*w0 + a1.x*w1)*inv;
        float o1 = (a0.y*w0 + a1.y*w1)*inv;
        float o2 = (a0.z*w0 + a1.z*w1)*inv;
        float o3 = (a0.w*w0 + a1.w*w1)*inv;
        uint32_t hh, ll;
        split2(o0, o1, hh, ll);
        *(uint32_t*)(oh + cc)     = hh; *(uint32_t*)(ol + cc)     = ll;
        split2(o2, o3, hh, ll);
        *(uint32_t*)(oh + cc + 2) = hh; *(uint32_t*)(ol + cc + 2) = ll;
    }
}

extern "C" void kernel_launch(void* const* d_in, const int* in_sizes, int n_in,
                              void* d_out, int out_size) {
    const float* x    = (const float*)d_in[0];
    const float* Wq   = (const float*)d_in[1];
    const float* Wk   = (const float*)d_in[2];
    const float* Wv   = (const float*)d_in[3];
    const float* Wo   = (const float*)d_in[4];
    const float* logc = (const float*)d_in[5];
    const float* logb = (const float*)d_in[6];
    if (in_sizes[0] != NB * SEQ * DM) {
        const float* xf = nullptr; const float* ws[4] = {}; const float* sc[2] = {};
        int nw = 0, ns = 0;
        for (int i = 0; i < n_in; i++) {
            if (in_sizes[i] == NB * SEQ * DM)          xf = (const float*)d_in[i];
            else if (in_sizes[i] == DM * DM && nw < 4) ws[nw++] = (const float*)d_in[i];
            else if (in_sizes[i] == 1 && ns < 2)       sc[ns++] = (const float*)d_in[i];
        }
        if (xf && nw == 4 && ns == 2) {
            x = xf; Wq = ws[0]; Wk = ws[1]; Wv = ws[2]; Wo = ws[3];
            logc = sc[0]; logb = sc[1];
        }
    }
    float* out = (float*)d_out;

    cudaFuncSetAttribute(attn_mma_kernel,    cudaFuncAttributeMaxDynamicSharedMemorySize, ATTN_SMEM);
    cudaFuncSetAttribute(mma_gemm_kernel<0>, cudaFuncAttributeMaxDynamicSharedMemorySize, GEMM_SMEM);
    cudaFuncSetAttribute(mma_gemm_kernel<1>, cudaFuncAttributeMaxDynamicSharedMemorySize, GEMM_SMEM);

    cvt_x_kernel<<<(MROWS*DM/4 + 255)/256, 256>>>(x, MROWS*DM);
    dim3 wgrid(DM*DM/4/256, 4);
    cvt_w_kernel<<<wgrid, 256>>>(Wq, Wk, Wv, Wo);

    dim3 pgrid(DM / 128, MROWS / 128, 3);
    mma_gemm_kernel<0><<<pgrid, 256, GEMM_SMEM>>>(nullptr);

    dim3 agrid(48, NH, NB);
    attn_mma_kernel<<<agrid, 128, ATTN_SMEM>>>(logc, logb);

    dim3 rgrid(16, NH, NB);
    attn_reduce_kernel<<<rgrid, 256>>>();

    dim3 ogrid(DM / 128, MROWS / 128, 1);
    mma_gemm_kernel<1><<<ogrid, 256, GEMM_SMEM>>>(out);
}